// round 5
// baseline (speedup 1.0000x reference)
#include <cuda_runtime.h>
#include <cuda_bf16.h>
#include <cstdint>

#define BATCH 16
#define NN 2048
#define DD 256

// ---------------- scratch (static device globals; no allocs) ----------------
__device__ __nv_bfloat16 d_Mhi[DD * DD];
__device__ __nv_bfloat16 d_Mlo[DD * DD];
__device__ __nv_bfloat16 d_Ghi[BATCH * NN * DD];
__device__ __nv_bfloat16 d_Glo[BATCH * NN * DD];
__device__ __nv_bfloat16 d_Xhi[BATCH * NN * DD];
__device__ __nv_bfloat16 d_Xlo[BATCH * NN * DD];
__device__ __nv_bfloat16 d_Xthi[BATCH * DD * NN];
__device__ __nv_bfloat16 d_Xtlo[BATCH * DD * NN];
__device__ float d_S[(size_t)BATCH * NN * NN];            // 256 MiB scores
__device__ __nv_bfloat16 d_Phi[(size_t)BATCH * NN * NN];  // 128 MiB P hi
__device__ __nv_bfloat16 d_Plo[(size_t)BATCH * NN * NN];  // 128 MiB P lo
__device__ float d_pm[(size_t)BATCH * NN * 32];
__device__ float d_pl[(size_t)BATCH * NN * 32];
__device__ float d_rm[BATCH * NN];
__device__ float d_rl[BATCH * NN];

// ---------------- helpers ----------------
__device__ __forceinline__ uint32_t smem_to_u32(const void* p) {
    uint32_t a;
    asm("{ .reg .u64 t; cvta.to.shared.u64 t, %1; cvt.u32.u64 %0, t; }" : "=r"(a) : "l"(p));
    return a;
}
__device__ __forceinline__ void split_hl(float v, float& h, float& l) {
    __nv_bfloat16 hb = __float2bfloat16(v);
    h = __bfloat162float(hb);
    l = v - h;
}
__device__ __forceinline__ uint32_t pack_bf2(float a, float b) {
    __nv_bfloat162 h = __floats2bfloat162_rn(a, b);
    return *(uint32_t*)&h;
}
__device__ __forceinline__ void ldmx4(uint32_t (&d)[4], uint32_t addr) {
    asm volatile("ldmatrix.sync.aligned.m8n8.x4.shared.b16 {%0,%1,%2,%3}, [%4];"
                 : "=r"(d[0]), "=r"(d[1]), "=r"(d[2]), "=r"(d[3]) : "r"(addr));
}
__device__ __forceinline__ void mma16816(float (&c)[4], const uint32_t (&a)[4],
                                         uint32_t b0, uint32_t b1) {
    asm volatile(
        "mma.sync.aligned.m16n8k16.row.col.f32.bf16.bf16.f32 "
        "{%0,%1,%2,%3}, {%4,%5,%6,%7}, {%8,%9}, {%0,%1,%2,%3};"
        : "+f"(c[0]), "+f"(c[1]), "+f"(c[2]), "+f"(c[3])
        : "r"(a[0]), "r"(a[1]), "r"(a[2]), "r"(a[3]), "r"(b0), "r"(b1));
}
__device__ __forceinline__ uint32_t swz(uint32_t byte) {
    return byte ^ ((byte >> 3) & 0x70);
}
__device__ __forceinline__ void cp16(uint32_t dst, const void* src) {
    asm volatile("cp.async.cg.shared.global [%0], [%1], 16;" :: "r"(dst), "l"(src));
}
#define CP_COMMIT() asm volatile("cp.async.commit_group;" ::: "memory")
#define CP_WAIT(n)  asm volatile("cp.async.wait_group %0;" :: "n"(n) : "memory")

// Stage a [ROWS x 64] bf16 tile (row stride = stride elems) into SW128 smem.
template <int ROWS>
__device__ __forceinline__ void stage_cp(uint32_t dst, const __nv_bfloat16* src,
                                         int stride, int tid) {
#pragma unroll
    for (int p = 0; p < ROWS / 32; ++p) {
        int i = tid + p * 256;
        int r = i >> 3, c = i & 7;
        cp16(dst + swz((uint32_t)(r * 128 + c * 16)), src + (size_t)r * stride + c * 8);
    }
}
__device__ __forceinline__ uint32_t tile_addr(uint32_t base, int rowbase, int kbyte, int lane) {
    int mat = lane >> 3, ri = lane & 7;
    int row = rowbase + (mat & 1) * 8 + ri;
    return base + swz((uint32_t)(row * 128 + kbyte + (mat >> 1) * 16));
}

// Warp computes 32x64 over one k=64 chunk, 3 passes (AhiBhi, AhiBlo, AloBhi).
__device__ __forceinline__ void mma_chunk3(float (&acc)[2][8][4],
                                           uint32_t aHi, uint32_t aLo,
                                           uint32_t bHi, uint32_t bLo,
                                           int mrow, int ncol, int lane) {
#pragma unroll
    for (int k16 = 0; k16 < 4; ++k16) {
        int kb = k16 * 32;
        uint32_t ah[2][4], bh[4][4];
        ldmx4(ah[0], tile_addr(aHi, mrow, kb, lane));
        ldmx4(ah[1], tile_addr(aHi, mrow + 16, kb, lane));
#pragma unroll
        for (int g = 0; g < 4; ++g) ldmx4(bh[g], tile_addr(bHi, ncol + g * 16, kb, lane));
#pragma unroll
        for (int mi = 0; mi < 2; ++mi)
#pragma unroll
            for (int g = 0; g < 4; ++g) {
                mma16816(acc[mi][g * 2 + 0], ah[mi], bh[g][0], bh[g][2]);
                mma16816(acc[mi][g * 2 + 1], ah[mi], bh[g][1], bh[g][3]);
            }
        {
            uint32_t bl[4][4];
#pragma unroll
            for (int g = 0; g < 4; ++g) ldmx4(bl[g], tile_addr(bLo, ncol + g * 16, kb, lane));
#pragma unroll
            for (int mi = 0; mi < 2; ++mi)
#pragma unroll
                for (int g = 0; g < 4; ++g) {
                    mma16816(acc[mi][g * 2 + 0], ah[mi], bl[g][0], bl[g][2]);
                    mma16816(acc[mi][g * 2 + 1], ah[mi], bl[g][1], bl[g][3]);
                }
        }
        {
            uint32_t al[2][4];
            ldmx4(al[0], tile_addr(aLo, mrow, kb, lane));
            ldmx4(al[1], tile_addr(aLo, mrow + 16, kb, lane));
#pragma unroll
            for (int mi = 0; mi < 2; ++mi)
#pragma unroll
                for (int g = 0; g < 4; ++g) {
                    mma16816(acc[mi][g * 2 + 0], al[mi], bh[g][0], bh[g][2]);
                    mma16816(acc[mi][g * 2 + 1], al[mi], bh[g][1], bh[g][3]);
                }
        }
    }
}

#define BUF 65536       // scores/gproj buffer set: Ahi|Alo|Bhi|Blo, 16KB each
#define ADJ_SM 131072   // adj smem offset in scores (64KB region)

// ---------------------------------------------------------------------------
// K1: M = W @ W^T  -> hi/lo bf16
// ---------------------------------------------------------------------------
__global__ void wwt_kernel(const float* __restrict__ W) {
    __shared__ float sR[16][257];
    __shared__ float sC[16][257];
    int tx = threadIdx.x, ty = threadIdx.y;
    int t = ty * 16 + tx;
    int r0 = blockIdx.y * 16, c0 = blockIdx.x * 16;
    {
        int row = t >> 4, base = t & 15;
#pragma unroll
        for (int p = 0; p < 16; ++p) {
            int col = base + p * 16;
            sR[row][col] = W[(r0 + row) * DD + col];
            sC[row][col] = W[(c0 + row) * DD + col];
        }
    }
    __syncthreads();
    float acc = 0.f;
#pragma unroll 8
    for (int k = 0; k < DD; ++k) acc += sR[ty][k] * sC[tx][k];
    float h, l;
    split_hl(acc, h, l);
    d_Mhi[(r0 + ty) * DD + (c0 + tx)] = __float2bfloat16(h);
    d_Mlo[(r0 + ty) * DD + (c0 + tx)] = __float2bfloat16(l);
}

// ---------------------------------------------------------------------------
// K2: X -> Xhi/Xlo (row-major) + Xthi/Xtlo ([b][d][m])
// ---------------------------------------------------------------------------
__global__ __launch_bounds__(256) void convx_kernel(const float* __restrict__ X) {
    __shared__ float tile[32][33];
    int b = blockIdx.z;
    int m0 = blockIdx.y * 32, d0 = blockIdx.x * 32;
    int j = threadIdx.x & 31, i0 = threadIdx.x >> 5;
    const float* Xb = X + (size_t)b * NN * DD;
#pragma unroll
    for (int i = i0; i < 32; i += 8) {
        float v = Xb[(size_t)(m0 + i) * DD + d0 + j];
        tile[i][j] = v;
        float h, l;
        split_hl(v, h, l);
        size_t idx = (size_t)b * NN * DD + (size_t)(m0 + i) * DD + d0 + j;
        d_Xhi[idx] = __float2bfloat16(h);
        d_Xlo[idx] = __float2bfloat16(l);
    }
    __syncthreads();
#pragma unroll
    for (int i = i0; i < 32; i += 8) {
        float v = tile[j][i];
        float h, l;
        split_hl(v, h, l);
        size_t idx = (size_t)b * DD * NN + (size_t)(d0 + i) * NN + m0 + j;
        d_Xthi[idx] = __float2bfloat16(h);
        d_Xtlo[idx] = __float2bfloat16(l);
    }
}

// ---------------------------------------------------------------------------
// K3: G = X @ M (mma, pipelined).  grid (nh=2, tile=256).
// ---------------------------------------------------------------------------
__global__ __launch_bounds__(256) void gproj_kernel() {
    extern __shared__ __align__(128) char sm[];
    uint32_t base = smem_to_u32(sm);
    int tid = threadIdx.x, lane = tid & 31, wid = tid >> 5;
    int nh = blockIdx.x, ti = blockIdx.y;
    int mrow = (wid >> 1) * 32, ncol = (wid & 1) * 64;

    float acc[2][8][4];
#pragma unroll
    for (int mi = 0; mi < 2; ++mi)
#pragma unroll
        for (int nf = 0; nf < 8; ++nf)
#pragma unroll
            for (int q = 0; q < 4; ++q) acc[mi][nf][q] = 0.f;

    const __nv_bfloat16* Ahi = d_Xhi + (size_t)ti * 128 * DD;
    const __nv_bfloat16* Alo = d_Xlo + (size_t)ti * 128 * DD;
    const __nv_bfloat16* Bhi = d_Mhi + nh * 128 * DD;
    const __nv_bfloat16* Blo = d_Mlo + nh * 128 * DD;

    stage_cp<128>(base, Ahi, DD, tid);
    stage_cp<128>(base + 16384, Alo, DD, tid);
    stage_cp<128>(base + 32768, Bhi, DD, tid);
    stage_cp<128>(base + 49152, Blo, DD, tid);
    CP_COMMIT();

    for (int kc = 0; kc < 4; ++kc) {
        if (kc < 3) {
            uint32_t nb = base + ((kc + 1) & 1) * BUF;
            stage_cp<128>(nb, Ahi + (kc + 1) * 64, DD, tid);
            stage_cp<128>(nb + 16384, Alo + (kc + 1) * 64, DD, tid);
            stage_cp<128>(nb + 32768, Bhi + (kc + 1) * 64, DD, tid);
            stage_cp<128>(nb + 49152, Blo + (kc + 1) * 64, DD, tid);
            CP_COMMIT();
            CP_WAIT(1);
        } else {
            CP_WAIT(0);
        }
        __syncthreads();
        uint32_t cb = base + (kc & 1) * BUF;
        mma_chunk3(acc, cb, cb + 16384, cb + 32768, cb + 49152, mrow, ncol, lane);
        __syncthreads();
    }
#pragma unroll
    for (int mi = 0; mi < 2; ++mi) {
        int rA = ti * 128 + mrow + mi * 16 + (lane >> 2);
        int rB = rA + 8;
#pragma unroll
        for (int nf = 0; nf < 8; ++nf) {
            int col = nh * 128 + ncol + nf * 8 + (lane & 3) * 2;
            float h0, l0, h1, l1;
            split_hl(acc[mi][nf][0], h0, l0);
            split_hl(acc[mi][nf][1], h1, l1);
            *(uint32_t*)&d_Ghi[(size_t)rA * DD + col] = pack_bf2(h0, h1);
            *(uint32_t*)&d_Glo[(size_t)rA * DD + col] = pack_bf2(l0, l1);
            split_hl(acc[mi][nf][2], h0, l0);
            split_hl(acc[mi][nf][3], h1, l1);
            *(uint32_t*)&d_Ghi[(size_t)rB * DD + col] = pack_bf2(h0, h1);
            *(uint32_t*)&d_Glo[(size_t)rB * DD + col] = pack_bf2(l0, l1);
        }
    }
}

// ---------------------------------------------------------------------------
// K4: scores tile (nt, rt, b), pipelined; adj prefetched to smem during MMA.
// ---------------------------------------------------------------------------
__global__ __launch_bounds__(256) void scores_kernel(const float* __restrict__ ADJ) {
    extern __shared__ __align__(128) char sm[];
    uint32_t base = smem_to_u32(sm);
    float* adjS = (float*)(sm + ADJ_SM);       // 128 x 128 fp32
    int tid = threadIdx.x, lane = tid & 31, wid = tid >> 5;
    int nt = blockIdx.x, rt = blockIdx.y, b = blockIdx.z;
    int mrow = (wid >> 1) * 32, ncol = (wid & 1) * 64;

    float acc[2][8][4];
#pragma unroll
    for (int mi = 0; mi < 2; ++mi)
#pragma unroll
        for (int nf = 0; nf < 8; ++nf)
#pragma unroll
            for (int q = 0; q < 4; ++q) acc[mi][nf][q] = 0.f;

    const __nv_bfloat16* Ahi = d_Ghi + ((size_t)b * NN + rt * 128) * DD;
    const __nv_bfloat16* Alo = d_Glo + ((size_t)b * NN + rt * 128) * DD;
    const __nv_bfloat16* Bhi = d_Xhi + ((size_t)b * NN + nt * 128) * DD;
    const __nv_bfloat16* Blo = d_Xlo + ((size_t)b * NN + nt * 128) * DD;
    const float* adjG = ADJ + ((size_t)b * NN + rt * 128) * NN + nt * 128;
    uint32_t adjB = base + ADJ_SM;

    stage_cp<128>(base, Ahi, DD, tid);
    stage_cp<128>(base + 16384, Alo, DD, tid);
    stage_cp<128>(base + 32768, Bhi, DD, tid);
    stage_cp<128>(base + 49152, Blo, DD, tid);
    CP_COMMIT();

    for (int kc = 0; kc < 4; ++kc) {
        // stage next operand buffers + a quarter of the adj tile
        if (kc < 3) {
            uint32_t nb = base + ((kc + 1) & 1) * BUF;
            stage_cp<128>(nb, Ahi + (kc + 1) * 64, DD, tid);
            stage_cp<128>(nb + 16384, Alo + (kc + 1) * 64, DD, tid);
            stage_cp<128>(nb + 32768, Bhi + (kc + 1) * 64, DD, tid);
            stage_cp<128>(nb + 49152, Blo + (kc + 1) * 64, DD, tid);
        }
#pragma unroll
        for (int p = 0; p < 4; ++p) {
            int i = tid + (kc * 4 + p) * 256;
            int r = i >> 5, c = i & 31;
            cp16(adjB + (uint32_t)(r * 512 + c * 16), adjG + (size_t)r * NN + c * 4);
        }
        CP_COMMIT();
        if (kc < 3) { CP_WAIT(1); } else { CP_WAIT(0); }
        __syncthreads();
        uint32_t cb = base + (kc & 1) * BUF;
        mma_chunk3(acc, cb, cb + 16384, cb + 32768, cb + 49152, mrow, ncol, lane);
        __syncthreads();
    }
    CP_WAIT(0);
    __syncthreads();

    // epilogue: leaky -> *adj(smem) -> write S; per-(row, 64col) max & sumexp
    int cl0 = ncol + (lane & 3) * 2;
    float mx[2][2] = {{-1e30f, -1e30f}, {-1e30f, -1e30f}};
#pragma unroll
    for (int mi = 0; mi < 2; ++mi) {
        int rl = mrow + mi * 16 + (lane >> 2);
        int rA = rt * 128 + rl;
        int rB = rA + 8;
        float* swA = d_S + ((size_t)b * NN + rA) * NN + nt * 128;
        float* swB = d_S + ((size_t)b * NN + rB) * NN + nt * 128;
#pragma unroll
        for (int nf = 0; nf < 8; ++nf) {
            int c = cl0 + nf * 8;
            float2 aA = *(float2*)&adjS[rl * 128 + c];
            float2 aB = *(float2*)&adjS[(rl + 8) * 128 + c];
            float v0 = acc[mi][nf][0]; v0 = fmaxf(v0, 0.2f * v0) * aA.x;
            float v1 = acc[mi][nf][1]; v1 = fmaxf(v1, 0.2f * v1) * aA.y;
            float v2 = acc[mi][nf][2]; v2 = fmaxf(v2, 0.2f * v2) * aB.x;
            float v3 = acc[mi][nf][3]; v3 = fmaxf(v3, 0.2f * v3) * aB.y;
            acc[mi][nf][0] = v0; acc[mi][nf][1] = v1;
            acc[mi][nf][2] = v2; acc[mi][nf][3] = v3;
            *(float2*)&swA[c] = make_float2(v0, v1);
            *(float2*)&swB[c] = make_float2(v2, v3);
            mx[mi][0] = fmaxf(mx[mi][0], fmaxf(v0, v1));
            mx[mi][1] = fmaxf(mx[mi][1], fmaxf(v2, v3));
        }
    }
#pragma unroll
    for (int mi = 0; mi < 2; ++mi)
#pragma unroll
        for (int h = 0; h < 2; ++h) {
            mx[mi][h] = fmaxf(mx[mi][h], __shfl_xor_sync(0xffffffffu, mx[mi][h], 1));
            mx[mi][h] = fmaxf(mx[mi][h], __shfl_xor_sync(0xffffffffu, mx[mi][h], 2));
        }
    float sum[2][2] = {{0.f, 0.f}, {0.f, 0.f}};
#pragma unroll
    for (int mi = 0; mi < 2; ++mi)
#pragma unroll
        for (int nf = 0; nf < 8; ++nf) {
            sum[mi][0] += __expf(acc[mi][nf][0] - mx[mi][0]) + __expf(acc[mi][nf][1] - mx[mi][0]);
            sum[mi][1] += __expf(acc[mi][nf][2] - mx[mi][1]) + __expf(acc[mi][nf][3] - mx[mi][1]);
        }
#pragma unroll
    for (int mi = 0; mi < 2; ++mi)
#pragma unroll
        for (int h = 0; h < 2; ++h) {
            sum[mi][h] += __shfl_xor_sync(0xffffffffu, sum[mi][h], 1);
            sum[mi][h] += __shfl_xor_sync(0xffffffffu, sum[mi][h], 2);
        }
    if ((lane & 3) == 0) {
        int pi = nt * 2 + (wid & 1);
#pragma unroll
        for (int mi = 0; mi < 2; ++mi)
#pragma unroll
            for (int h = 0; h < 2; ++h) {
                int row = rt * 128 + mrow + mi * 16 + (lane >> 2) + h * 8;
                size_t idx = (((size_t)b * NN + row) << 5) + pi;
                d_pm[idx] = mx[mi][h];
                d_pl[idx] = sum[mi][h];
            }
    }
}

// ---------------------------------------------------------------------------
// K5: merge partials -> d_rm, d_rl
// ---------------------------------------------------------------------------
__global__ void reduce_kernel() {
    int i = blockIdx.x * 256 + threadIdx.x;
    const float* pm = d_pm + ((size_t)i << 5);
    const float* pl = d_pl + ((size_t)i << 5);
    float m = -1e30f;
#pragma unroll
    for (int j = 0; j < 32; ++j) m = fmaxf(m, pm[j]);
    float l = 0.f;
#pragma unroll
    for (int j = 0; j < 32; ++j) l += pl[j] * __expf(pm[j] - m);
    d_rm[i] = m;
    d_rl[i] = l;
}

// ---------------------------------------------------------------------------
// K6: S -> P hi/lo bf16  (p = exp(s - m) / l)
// ---------------------------------------------------------------------------
__global__ __launch_bounds__(256) void expp_kernel() {
    size_t i = ((size_t)blockIdx.x * 256 + threadIdx.x) * 8;
    int row = (int)(i >> 11);
    float m = d_rm[row];
    float linv = 1.f / d_rl[row];
    float4 s0 = *(const float4*)&d_S[i];
    float4 s1 = *(const float4*)&d_S[i + 4];
    float p[8];
    p[0] = __expf(s0.x - m) * linv;
    p[1] = __expf(s0.y - m) * linv;
    p[2] = __expf(s0.z - m) * linv;
    p[3] = __expf(s0.w - m) * linv;
    p[4] = __expf(s1.x - m) * linv;
    p[5] = __expf(s1.y - m) * linv;
    p[6] = __expf(s1.z - m) * linv;
    p[7] = __expf(s1.w - m) * linv;
    float h[8], l[8];
#pragma unroll
    for (int q = 0; q < 8; ++q) split_hl(p[q], h[q], l[q]);
    *(uint4*)&d_Phi[i] = make_uint4(pack_bf2(h[0], h[1]), pack_bf2(h[2], h[3]),
                                    pack_bf2(h[4], h[5]), pack_bf2(h[6], h[7]));
    *(uint4*)&d_Plo[i] = make_uint4(pack_bf2(l[0], l[1]), pack_bf2(l[2], l[3]),
                                    pack_bf2(l[4], l[5]), pack_bf2(l[6], l[7]));
}

// ---------------------------------------------------------------------------
// K7: PV, pipelined.  grid (rt=32, b=16).  64 rows x full 256 cols per CTA.
// Buffer set: Phi 8KB | Plo 8KB | Bthi 32KB | Btlo 32KB = 80KB, x2 = 160KB.
// ---------------------------------------------------------------------------
#define PBUF 81920
__global__ __launch_bounds__(256) void pv_kernel(const float* __restrict__ bias,
                                                 float* __restrict__ OUT) {
    extern __shared__ __align__(128) char sm[];
    uint32_t base = smem_to_u32(sm);
    int tid = threadIdx.x, lane = tid & 31, wid = tid >> 5;
    int rt = blockIdx.x, b = blockIdx.y;
    int mrow = (wid >> 2) * 32, ncol = (wid & 3) * 64;

    float acc[2][8][4];
#pragma unroll
    for (int mi = 0; mi < 2; ++mi)
#pragma unroll
        for (int nf = 0; nf < 8; ++nf)
#pragma unroll
            for (int q = 0; q < 4; ++q) acc[mi][nf][q] = 0.f;

    const __nv_bfloat16* Phi = d_Phi + ((size_t)b * NN + rt * 64) * NN;
    const __nv_bfloat16* Plo = d_Plo + ((size_t)b * NN + rt * 64) * NN;
    const __nv_bfloat16* Bthi = d_Xthi + (size_t)b * DD * NN;
    const __nv_bfloat16* Btlo = d_Xtlo + (size_t)b * DD * NN;

    stage_cp<64>(base, Phi, NN, tid);
    stage_cp<64>(base + 8192, Plo, NN, tid);
    stage_cp<256>(base + 16384, Bthi, NN, tid);
    stage_cp<256>(base + 49152, Btlo, NN, tid);
    CP_COMMIT();

    for (int kt = 0; kt < 32; ++kt) {
        if (kt < 31) {
            uint32_t nb = base + ((kt + 1) & 1) * PBUF;
            int k0 = (kt + 1) * 64;
            stage_cp<64>(nb, Phi + k0, NN, tid);
            stage_cp<64>(nb + 8192, Plo + k0, NN, tid);
            stage_cp<256>(nb + 16384, Bthi + k0, NN, tid);
            stage_cp<256>(nb + 49152, Btlo + k0, NN, tid);
            CP_COMMIT();
            CP_WAIT(1);
        } else {
            CP_WAIT(0);
        }
        __syncthreads();
        uint32_t cb = base + (kt & 1) * PBUF;
        mma_chunk3(acc, cb, cb + 8192, cb + 16384, cb + 49152, mrow, ncol, lane);
        __syncthreads();
    }

#pragma unroll
    for (int mi = 0; mi < 2; ++mi) {
        int rA = rt * 64 + mrow + mi * 16 + (lane >> 2);
        int rB = rA + 8;
#pragma unroll
        for (int nf = 0; nf < 8; ++nf) {
            int col = ncol + nf * 8 + (lane & 3) * 2;
            float2 bv = *(const float2*)&bias[col];
            *(float2*)&OUT[((size_t)b * NN + rA) * DD + col] =
                make_float2(acc[mi][nf][0] + bv.x, acc[mi][nf][1] + bv.y);
            *(float2*)&OUT[((size_t)b * NN + rB) * DD + col] =
                make_float2(acc[mi][nf][2] + bv.x, acc[mi][nf][3] + bv.y);
        }
    }
}

// ---------------------------------------------------------------------------
extern "C" void kernel_launch(void* const* d_in, const int* in_sizes, int n_in,
                              void* d_out, int out_size) {
    const float* x    = (const float*)d_in[0];
    const float* adj  = (const float*)d_in[1];
    const float* W    = (const float*)d_in[2];
    const float* bias = (const float*)d_in[3];
    float* out = (float*)d_out;

    wwt_kernel<<<dim3(16, 16), dim3(16, 16)>>>(W);
    convx_kernel<<<dim3(8, 64, 16), 256>>>(x);

    const int SMB_G = 2 * BUF;            // 128 KB
    const int SMB_S = 2 * BUF + 65536;    // 192 KB (buffers + adj)
    const int SMB_P = 2 * PBUF;           // 160 KB
    cudaFuncSetAttribute(gproj_kernel, cudaFuncAttributeMaxDynamicSharedMemorySize, SMB_G);
    cudaFuncSetAttribute(scores_kernel, cudaFuncAttributeMaxDynamicSharedMemorySize, SMB_S);
    cudaFuncSetAttribute(pv_kernel, cudaFuncAttributeMaxDynamicSharedMemorySize, SMB_P);

    gproj_kernel<<<dim3(2, 256), 256, SMB_G>>>();
    scores_kernel<<<dim3(16, 16, 16), 256, SMB_S>>>(adj);
    reduce_kernel<<<BATCH * NN / 256, 256>>>();
    expp_kernel<<<(int)((size_t)BATCH * NN * NN / 2048), 256>>>();
    pv_kernel<<<dim3(32, 16), 256, SMB_P>>>(bias, out);
}

// round 6
// speedup vs baseline: 1.1356x; 1.1356x over previous
#include <cuda_runtime.h>
#include <cuda_bf16.h>
#include <cstdint>

#define BATCH 16
#define NN 2048
#define DD 256

// ---------------- scratch (static device globals; no allocs) ----------------
__device__ __nv_bfloat16 d_Mhi[DD * DD];
__device__ __nv_bfloat16 d_Mlo[DD * DD];
__device__ __nv_bfloat16 d_Ghi[BATCH * NN * DD];
__device__ __nv_bfloat16 d_Glo[BATCH * NN * DD];
__device__ __nv_bfloat16 d_Xhi[BATCH * NN * DD];
__device__ __nv_bfloat16 d_Xlo[BATCH * NN * DD];
__device__ __nv_bfloat16 d_Xthi[BATCH * DD * NN];
__device__ __nv_bfloat16 d_Xtlo[BATCH * DD * NN];
__device__ float d_S[(size_t)BATCH * NN * NN];            // 256 MiB scores
__device__ __nv_bfloat16 d_Phi[(size_t)BATCH * NN * NN];  // 128 MiB P hi
__device__ __nv_bfloat16 d_Plo[(size_t)BATCH * NN * NN];  // 128 MiB P lo
__device__ float d_pm[(size_t)BATCH * NN * 32];
__device__ float d_pl[(size_t)BATCH * NN * 32];
__device__ float d_rm[BATCH * NN];
__device__ float d_rl[BATCH * NN];

// ---------------- helpers ----------------
__device__ __forceinline__ uint32_t smem_to_u32(const void* p) {
    uint32_t a;
    asm("{ .reg .u64 t; cvta.to.shared.u64 t, %1; cvt.u32.u64 %0, t; }" : "=r"(a) : "l"(p));
    return a;
}
__device__ __forceinline__ void split_hl(float v, float& h, float& l) {
    __nv_bfloat16 hb = __float2bfloat16(v);
    h = __bfloat162float(hb);
    l = v - h;
}
__device__ __forceinline__ uint32_t pack_bf2(float a, float b) {
    __nv_bfloat162 h = __floats2bfloat162_rn(a, b);
    return *(uint32_t*)&h;
}
__device__ __forceinline__ void ldmx4(uint32_t (&d)[4], uint32_t addr) {
    asm volatile("ldmatrix.sync.aligned.m8n8.x4.shared.b16 {%0,%1,%2,%3}, [%4];"
                 : "=r"(d[0]), "=r"(d[1]), "=r"(d[2]), "=r"(d[3]) : "r"(addr));
}
__device__ __forceinline__ void mma16816(float (&c)[4], const uint32_t (&a)[4],
                                         uint32_t b0, uint32_t b1) {
    asm volatile(
        "mma.sync.aligned.m16n8k16.row.col.f32.bf16.bf16.f32 "
        "{%0,%1,%2,%3}, {%4,%5,%6,%7}, {%8,%9}, {%0,%1,%2,%3};"
        : "+f"(c[0]), "+f"(c[1]), "+f"(c[2]), "+f"(c[3])
        : "r"(a[0]), "r"(a[1]), "r"(a[2]), "r"(a[3]), "r"(b0), "r"(b1));
}
__device__ __forceinline__ uint32_t swz(uint32_t byte) {
    return byte ^ ((byte >> 3) & 0x70);
}
__device__ __forceinline__ void cp16(uint32_t dst, const void* src) {
    asm volatile("cp.async.cg.shared.global [%0], [%1], 16;" :: "r"(dst), "l"(src));
}
#define CP_COMMIT() asm volatile("cp.async.commit_group;" ::: "memory")
#define CP_WAIT(n)  asm volatile("cp.async.wait_group %0;" :: "n"(n) : "memory")

// Stage a [ROWS x 64] bf16 tile (row stride = stride elems) into SW128 smem.
template <int ROWS>
__device__ __forceinline__ void stage_cp(uint32_t dst, const __nv_bfloat16* src,
                                         int stride, int tid) {
#pragma unroll
    for (int p = 0; p < ROWS / 32; ++p) {
        int i = tid + p * 256;
        int r = i >> 3, c = i & 7;
        cp16(dst + swz((uint32_t)(r * 128 + c * 16)), src + (size_t)r * stride + c * 8);
    }
}
__device__ __forceinline__ uint32_t tile_addr(uint32_t base, int rowbase, int kbyte, int lane) {
    int mat = lane >> 3, ri = lane & 7;
    int row = rowbase + (mat & 1) * 8 + ri;
    return base + swz((uint32_t)(row * 128 + kbyte + (mat >> 1) * 16));
}

// Warp computes 32x64 over one k=64 chunk, 3 passes (AhiBhi, AloBhi, AhiBlo).
// Register-lean schedule: B fragments processed in pairs.
__device__ __forceinline__ void mma_chunk3(float (&acc)[2][8][4],
                                           uint32_t aHi, uint32_t aLo,
                                           uint32_t bHi, uint32_t bLo,
                                           int mrow, int ncol, int lane) {
#pragma unroll
    for (int k16 = 0; k16 < 4; ++k16) {
        int kb = k16 * 32;
        uint32_t ah[2][4], al[2][4];
        ldmx4(ah[0], tile_addr(aHi, mrow, kb, lane));
        ldmx4(ah[1], tile_addr(aHi, mrow + 16, kb, lane));
        ldmx4(al[0], tile_addr(aLo, mrow, kb, lane));
        ldmx4(al[1], tile_addr(aLo, mrow + 16, kb, lane));
#pragma unroll
        for (int gp = 0; gp < 4; gp += 2) {
            uint32_t b0[4], b1[4];
            ldmx4(b0, tile_addr(bHi, ncol + gp * 16, kb, lane));
            ldmx4(b1, tile_addr(bHi, ncol + (gp + 1) * 16, kb, lane));
#pragma unroll
            for (int mi = 0; mi < 2; ++mi) {
                mma16816(acc[mi][gp * 2 + 0], ah[mi], b0[0], b0[2]);
                mma16816(acc[mi][gp * 2 + 1], ah[mi], b0[1], b0[3]);
                mma16816(acc[mi][gp * 2 + 2], ah[mi], b1[0], b1[2]);
                mma16816(acc[mi][gp * 2 + 3], ah[mi], b1[1], b1[3]);
            }
#pragma unroll
            for (int mi = 0; mi < 2; ++mi) {
                mma16816(acc[mi][gp * 2 + 0], al[mi], b0[0], b0[2]);
                mma16816(acc[mi][gp * 2 + 1], al[mi], b0[1], b0[3]);
                mma16816(acc[mi][gp * 2 + 2], al[mi], b1[0], b1[2]);
                mma16816(acc[mi][gp * 2 + 3], al[mi], b1[1], b1[3]);
            }
            uint32_t c0[4], c1[4];
            ldmx4(c0, tile_addr(bLo, ncol + gp * 16, kb, lane));
            ldmx4(c1, tile_addr(bLo, ncol + (gp + 1) * 16, kb, lane));
#pragma unroll
            for (int mi = 0; mi < 2; ++mi) {
                mma16816(acc[mi][gp * 2 + 0], ah[mi], c0[0], c0[2]);
                mma16816(acc[mi][gp * 2 + 1], ah[mi], c0[1], c0[3]);
                mma16816(acc[mi][gp * 2 + 2], ah[mi], c1[0], c1[2]);
                mma16816(acc[mi][gp * 2 + 3], ah[mi], c1[1], c1[3]);
            }
        }
    }
}

// ---------------------------------------------------------------------------
// K1: M = W @ W^T  -> hi/lo bf16
// ---------------------------------------------------------------------------
__global__ void wwt_kernel(const float* __restrict__ W) {
    __shared__ float sR[16][257];
    __shared__ float sC[16][257];
    int tx = threadIdx.x, ty = threadIdx.y;
    int t = ty * 16 + tx;
    int r0 = blockIdx.y * 16, c0 = blockIdx.x * 16;
    {
        int row = t >> 4, base = t & 15;
#pragma unroll
        for (int p = 0; p < 16; ++p) {
            int col = base + p * 16;
            sR[row][col] = W[(r0 + row) * DD + col];
            sC[row][col] = W[(c0 + row) * DD + col];
        }
    }
    __syncthreads();
    float acc = 0.f;
#pragma unroll 8
    for (int k = 0; k < DD; ++k) acc += sR[ty][k] * sC[tx][k];
    float h, l;
    split_hl(acc, h, l);
    d_Mhi[(r0 + ty) * DD + (c0 + tx)] = __float2bfloat16(h);
    d_Mlo[(r0 + ty) * DD + (c0 + tx)] = __float2bfloat16(l);
}

// ---------------------------------------------------------------------------
// K2: X -> Xhi/Xlo (row-major) + Xthi/Xtlo ([b][d][m])
// ---------------------------------------------------------------------------
__global__ __launch_bounds__(256) void convx_kernel(const float* __restrict__ X) {
    __shared__ float tile[32][33];
    int b = blockIdx.z;
    int m0 = blockIdx.y * 32, d0 = blockIdx.x * 32;
    int j = threadIdx.x & 31, i0 = threadIdx.x >> 5;
    const float* Xb = X + (size_t)b * NN * DD;
#pragma unroll
    for (int i = i0; i < 32; i += 8) {
        float v = Xb[(size_t)(m0 + i) * DD + d0 + j];
        tile[i][j] = v;
        float h, l;
        split_hl(v, h, l);
        size_t idx = (size_t)b * NN * DD + (size_t)(m0 + i) * DD + d0 + j;
        d_Xhi[idx] = __float2bfloat16(h);
        d_Xlo[idx] = __float2bfloat16(l);
    }
    __syncthreads();
#pragma unroll
    for (int i = i0; i < 32; i += 8) {
        float v = tile[j][i];
        float h, l;
        split_hl(v, h, l);
        size_t idx = (size_t)b * DD * NN + (size_t)(d0 + i) * NN + m0 + j;
        d_Xthi[idx] = __float2bfloat16(h);
        d_Xtlo[idx] = __float2bfloat16(l);
    }
}

// ---------------------------------------------------------------------------
// K3: G = X @ M.  Single-buffer 64KB, occ 2.  grid (nh=2, tile=256).
// ---------------------------------------------------------------------------
__global__ __launch_bounds__(256, 2) void gproj_kernel() {
    extern __shared__ __align__(128) char sm[];
    uint32_t base = smem_to_u32(sm);
    int tid = threadIdx.x, lane = tid & 31, wid = tid >> 5;
    int nh = blockIdx.x, ti = blockIdx.y;
    int mrow = (wid >> 1) * 32, ncol = (wid & 1) * 64;

    float acc[2][8][4];
#pragma unroll
    for (int mi = 0; mi < 2; ++mi)
#pragma unroll
        for (int nf = 0; nf < 8; ++nf)
#pragma unroll
            for (int q = 0; q < 4; ++q) acc[mi][nf][q] = 0.f;

    const __nv_bfloat16* Ahi = d_Xhi + (size_t)ti * 128 * DD;
    const __nv_bfloat16* Alo = d_Xlo + (size_t)ti * 128 * DD;
    const __nv_bfloat16* Bhi = d_Mhi + nh * 128 * DD;
    const __nv_bfloat16* Blo = d_Mlo + nh * 128 * DD;

    for (int kc = 0; kc < 4; ++kc) {
        stage_cp<128>(base, Ahi + kc * 64, DD, tid);
        stage_cp<128>(base + 16384, Alo + kc * 64, DD, tid);
        stage_cp<128>(base + 32768, Bhi + kc * 64, DD, tid);
        stage_cp<128>(base + 49152, Blo + kc * 64, DD, tid);
        CP_COMMIT();
        CP_WAIT(0);
        __syncthreads();
        mma_chunk3(acc, base, base + 16384, base + 32768, base + 49152, mrow, ncol, lane);
        __syncthreads();
    }
#pragma unroll
    for (int mi = 0; mi < 2; ++mi) {
        int rA = ti * 128 + mrow + mi * 16 + (lane >> 2);
        int rB = rA + 8;
#pragma unroll
        for (int nf = 0; nf < 8; ++nf) {
            int col = nh * 128 + ncol + nf * 8 + (lane & 3) * 2;
            float h0, l0, h1, l1;
            split_hl(acc[mi][nf][0], h0, l0);
            split_hl(acc[mi][nf][1], h1, l1);
            *(uint32_t*)&d_Ghi[(size_t)rA * DD + col] = pack_bf2(h0, h1);
            *(uint32_t*)&d_Glo[(size_t)rA * DD + col] = pack_bf2(l0, l1);
            split_hl(acc[mi][nf][2], h0, l0);
            split_hl(acc[mi][nf][3], h1, l1);
            *(uint32_t*)&d_Ghi[(size_t)rB * DD + col] = pack_bf2(h0, h1);
            *(uint32_t*)&d_Glo[(size_t)rB * DD + col] = pack_bf2(l0, l1);
        }
    }
}

// ---------------------------------------------------------------------------
// K4: scores tile (nt, rt, b).  Single-buffer 64KB, occ 2, adj via gmem.
// ---------------------------------------------------------------------------
__global__ __launch_bounds__(256, 2) void scores_kernel(const float* __restrict__ ADJ) {
    extern __shared__ __align__(128) char sm[];
    uint32_t base = smem_to_u32(sm);
    int tid = threadIdx.x, lane = tid & 31, wid = tid >> 5;
    int nt = blockIdx.x, rt = blockIdx.y, b = blockIdx.z;
    int mrow = (wid >> 1) * 32, ncol = (wid & 1) * 64;

    float acc[2][8][4];
#pragma unroll
    for (int mi = 0; mi < 2; ++mi)
#pragma unroll
        for (int nf = 0; nf < 8; ++nf)
#pragma unroll
            for (int q = 0; q < 4; ++q) acc[mi][nf][q] = 0.f;

    const __nv_bfloat16* Ahi = d_Ghi + ((size_t)b * NN + rt * 128) * DD;
    const __nv_bfloat16* Alo = d_Glo + ((size_t)b * NN + rt * 128) * DD;
    const __nv_bfloat16* Bhi = d_Xhi + ((size_t)b * NN + nt * 128) * DD;
    const __nv_bfloat16* Blo = d_Xlo + ((size_t)b * NN + nt * 128) * DD;

    for (int kc = 0; kc < 4; ++kc) {
        stage_cp<128>(base, Ahi + kc * 64, DD, tid);
        stage_cp<128>(base + 16384, Alo + kc * 64, DD, tid);
        stage_cp<128>(base + 32768, Bhi + kc * 64, DD, tid);
        stage_cp<128>(base + 49152, Blo + kc * 64, DD, tid);
        CP_COMMIT();
        CP_WAIT(0);
        __syncthreads();
        mma_chunk3(acc, base, base + 16384, base + 32768, base + 49152, mrow, ncol, lane);
        __syncthreads();
    }

    // epilogue: leaky -> *adj -> write S; per-(row, 64col) max & sumexp
    int cb0 = nt * 128 + ncol + (lane & 3) * 2;
    float mx[2][2] = {{-1e30f, -1e30f}, {-1e30f, -1e30f}};
#pragma unroll
    for (int mi = 0; mi < 2; ++mi) {
        int rA = rt * 128 + mrow + mi * 16 + (lane >> 2);
        int rB = rA + 8;
        const float* adjA = ADJ + ((size_t)b * NN + rA) * NN;
        const float* adjB = ADJ + ((size_t)b * NN + rB) * NN;
        float* swA = d_S + ((size_t)b * NN + rA) * NN;
        float* swB = d_S + ((size_t)b * NN + rB) * NN;
#pragma unroll
        for (int nf = 0; nf < 8; ++nf) {
            int c = cb0 + nf * 8;
            float2 aA = *(const float2*)&adjA[c];
            float2 aB = *(const float2*)&adjB[c];
            float v0 = acc[mi][nf][0]; v0 = fmaxf(v0, 0.2f * v0) * aA.x;
            float v1 = acc[mi][nf][1]; v1 = fmaxf(v1, 0.2f * v1) * aA.y;
            float v2 = acc[mi][nf][2]; v2 = fmaxf(v2, 0.2f * v2) * aB.x;
            float v3 = acc[mi][nf][3]; v3 = fmaxf(v3, 0.2f * v3) * aB.y;
            acc[mi][nf][0] = v0; acc[mi][nf][1] = v1;
            acc[mi][nf][2] = v2; acc[mi][nf][3] = v3;
            *(float2*)&swA[c] = make_float2(v0, v1);
            *(float2*)&swB[c] = make_float2(v2, v3);
            mx[mi][0] = fmaxf(mx[mi][0], fmaxf(v0, v1));
            mx[mi][1] = fmaxf(mx[mi][1], fmaxf(v2, v3));
        }
    }
#pragma unroll
    for (int mi = 0; mi < 2; ++mi)
#pragma unroll
        for (int h = 0; h < 2; ++h) {
            mx[mi][h] = fmaxf(mx[mi][h], __shfl_xor_sync(0xffffffffu, mx[mi][h], 1));
            mx[mi][h] = fmaxf(mx[mi][h], __shfl_xor_sync(0xffffffffu, mx[mi][h], 2));
        }
    float sum[2][2] = {{0.f, 0.f}, {0.f, 0.f}};
#pragma unroll
    for (int mi = 0; mi < 2; ++mi)
#pragma unroll
        for (int nf = 0; nf < 8; ++nf) {
            sum[mi][0] += __expf(acc[mi][nf][0] - mx[mi][0]) + __expf(acc[mi][nf][1] - mx[mi][0]);
            sum[mi][1] += __expf(acc[mi][nf][2] - mx[mi][1]) + __expf(acc[mi][nf][3] - mx[mi][1]);
        }
#pragma unroll
    for (int mi = 0; mi < 2; ++mi)
#pragma unroll
        for (int h = 0; h < 2; ++h) {
            sum[mi][h] += __shfl_xor_sync(0xffffffffu, sum[mi][h], 1);
            sum[mi][h] += __shfl_xor_sync(0xffffffffu, sum[mi][h], 2);
        }
    if ((lane & 3) == 0) {
        int pi = nt * 2 + (wid & 1);
#pragma unroll
        for (int mi = 0; mi < 2; ++mi)
#pragma unroll
            for (int h = 0; h < 2; ++h) {
                int row = rt * 128 + mrow + mi * 16 + (lane >> 2) + h * 8;
                size_t idx = (((size_t)b * NN + row) << 5) + pi;
                d_pm[idx] = mx[mi][h];
                d_pl[idx] = sum[mi][h];
            }
    }
}

// ---------------------------------------------------------------------------
// K5: merge partials -> d_rm, d_rl
// ---------------------------------------------------------------------------
__global__ void reduce_kernel() {
    int i = blockIdx.x * 256 + threadIdx.x;
    const float* pm = d_pm + ((size_t)i << 5);
    const float* pl = d_pl + ((size_t)i << 5);
    float m = -1e30f;
#pragma unroll
    for (int j = 0; j < 32; ++j) m = fmaxf(m, pm[j]);
    float l = 0.f;
#pragma unroll
    for (int j = 0; j < 32; ++j) l += pl[j] * __expf(pm[j] - m);
    d_rm[i] = m;
    d_rl[i] = l;
}

// ---------------------------------------------------------------------------
// K6: S -> P hi/lo bf16  (p = exp(s - m) / l)
// ---------------------------------------------------------------------------
__global__ __launch_bounds__(256) void expp_kernel() {
    size_t i = ((size_t)blockIdx.x * 256 + threadIdx.x) * 8;
    int row = (int)(i >> 11);
    float m = d_rm[row];
    float linv = 1.f / d_rl[row];
    float4 s0 = *(const float4*)&d_S[i];
    float4 s1 = *(const float4*)&d_S[i + 4];
    float p[8];
    p[0] = __expf(s0.x - m) * linv;
    p[1] = __expf(s0.y - m) * linv;
    p[2] = __expf(s0.z - m) * linv;
    p[3] = __expf(s0.w - m) * linv;
    p[4] = __expf(s1.x - m) * linv;
    p[5] = __expf(s1.y - m) * linv;
    p[6] = __expf(s1.z - m) * linv;
    p[7] = __expf(s1.w - m) * linv;
    float h[8], l[8];
#pragma unroll
    for (int q = 0; q < 8; ++q) split_hl(p[q], h[q], l[q]);
    *(uint4*)&d_Phi[i] = make_uint4(pack_bf2(h[0], h[1]), pack_bf2(h[2], h[3]),
                                    pack_bf2(h[4], h[5]), pack_bf2(h[6], h[7]));
    *(uint4*)&d_Plo[i] = make_uint4(pack_bf2(l[0], l[1]), pack_bf2(l[2], l[3]),
                                    pack_bf2(l[4], l[5]), pack_bf2(l[6], l[7]));
}

// ---------------------------------------------------------------------------
// K7: PV.  Single-buffer 80KB, occ 2.  grid (rt=32, b=16): 64 rows x 256 cols.
// ---------------------------------------------------------------------------
__global__ __launch_bounds__(256, 2) void pv_kernel(const float* __restrict__ bias,
                                                    float* __restrict__ OUT) {
    extern __shared__ __align__(128) char sm[];
    uint32_t base = smem_to_u32(sm);
    int tid = threadIdx.x, lane = tid & 31, wid = tid >> 5;
    int rt = blockIdx.x, b = blockIdx.y;
    int mrow = (wid >> 2) * 32, ncol = (wid & 3) * 64;

    float acc[2][8][4];
#pragma unroll
    for (int mi = 0; mi < 2; ++mi)
#pragma unroll
        for (int nf = 0; nf < 8; ++nf)
#pragma unroll
            for (int q = 0; q < 4; ++q) acc[mi][nf][q] = 0.f;

    const __nv_bfloat16* Phi = d_Phi + ((size_t)b * NN + rt * 64) * NN;
    const __nv_bfloat16* Plo = d_Plo + ((size_t)b * NN + rt * 64) * NN;
    const __nv_bfloat16* Bthi = d_Xthi + (size_t)b * DD * NN;
    const __nv_bfloat16* Btlo = d_Xtlo + (size_t)b * DD * NN;

    for (int kt = 0; kt < 32; ++kt) {
        int k0 = kt * 64;
        stage_cp<64>(base, Phi + k0, NN, tid);
        stage_cp<64>(base + 8192, Plo + k0, NN, tid);
        stage_cp<256>(base + 16384, Bthi + k0, NN, tid);
        stage_cp<256>(base + 49152, Btlo + k0, NN, tid);
        CP_COMMIT();
        CP_WAIT(0);
        __syncthreads();
        mma_chunk3(acc, base, base + 8192, base + 16384, base + 49152, mrow, ncol, lane);
        __syncthreads();
    }

#pragma unroll
    for (int mi = 0; mi < 2; ++mi) {
        int rA = rt * 64 + mrow + mi * 16 + (lane >> 2);
        int rB = rA + 8;
#pragma unroll
        for (int nf = 0; nf < 8; ++nf) {
            int col = ncol + nf * 8 + (lane & 3) * 2;
            float2 bv = *(const float2*)&bias[col];
            *(float2*)&OUT[((size_t)b * NN + rA) * DD + col] =
                make_float2(acc[mi][nf][0] + bv.x, acc[mi][nf][1] + bv.y);
            *(float2*)&OUT[((size_t)b * NN + rB) * DD + col] =
                make_float2(acc[mi][nf][2] + bv.x, acc[mi][nf][3] + bv.y);
        }
    }
}

// ---------------------------------------------------------------------------
extern "C" void kernel_launch(void* const* d_in, const int* in_sizes, int n_in,
                              void* d_out, int out_size) {
    const float* x    = (const float*)d_in[0];
    const float* adj  = (const float*)d_in[1];
    const float* W    = (const float*)d_in[2];
    const float* bias = (const float*)d_in[3];
    float* out = (float*)d_out;

    wwt_kernel<<<dim3(16, 16), dim3(16, 16)>>>(W);
    convx_kernel<<<dim3(8, 64, 16), 256>>>(x);

    const int SMB_G = 65536;   // single buffer set
    const int SMB_S = 65536;
    const int SMB_P = 81920;
    cudaFuncSetAttribute(gproj_kernel, cudaFuncAttributeMaxDynamicSharedMemorySize, SMB_G);
    cudaFuncSetAttribute(scores_kernel, cudaFuncAttributeMaxDynamicSharedMemorySize, SMB_S);
    cudaFuncSetAttribute(pv_kernel, cudaFuncAttributeMaxDynamicSharedMemorySize, SMB_P);

    gproj_kernel<<<dim3(2, 256), 256, SMB_G>>>();
    scores_kernel<<<dim3(16, 16, 16), 256, SMB_S>>>(adj);
    reduce_kernel<<<BATCH * NN / 256, 256>>>();
    expp_kernel<<<(int)((size_t)BATCH * NN * NN / 2048), 256>>>();
    pv_kernel<<<dim3(32, 16), 256, SMB_P>>>(bias, out);
}

// round 7
// speedup vs baseline: 1.1817x; 1.0405x over previous
#include <cuda_runtime.h>
#include <cuda_bf16.h>
#include <cstdint>

#define BATCH 16
#define NN 2048
#define DD 256

// ---------------- scratch (static device globals; no allocs) ----------------
__device__ __nv_bfloat16 d_Mhi[DD * DD];
__device__ __nv_bfloat16 d_Mlo[DD * DD];
__device__ __nv_bfloat16 d_Ghi[BATCH * NN * DD];
__device__ __nv_bfloat16 d_Glo[BATCH * NN * DD];
__device__ __nv_bfloat16 d_Xhi[BATCH * NN * DD];
__device__ __nv_bfloat16 d_Xlo[BATCH * NN * DD];
__device__ __nv_bfloat16 d_Xthi[BATCH * DD * NN];
__device__ __nv_bfloat16 d_Xtlo[BATCH * DD * NN];
__device__ float d_S[(size_t)BATCH * NN * NN];            // 256 MiB scores
__device__ float d_pm[(size_t)BATCH * NN * 64];           // per-(row, 32col-seg) max
__device__ float d_pl[(size_t)BATCH * NN * 64];           // per-(row, 32col-seg) sumexp
__device__ float d_rm[BATCH * NN];
__device__ float d_rl[BATCH * NN];

// ---------------- helpers ----------------
__device__ __forceinline__ uint32_t smem_to_u32(const void* p) {
    uint32_t a;
    asm("{ .reg .u64 t; cvta.to.shared.u64 t, %1; cvt.u32.u64 %0, t; }" : "=r"(a) : "l"(p));
    return a;
}
__device__ __forceinline__ void split_hl(float v, float& h, float& l) {
    __nv_bfloat16 hb = __float2bfloat16(v);
    h = __bfloat162float(hb);
    l = v - h;
}
__device__ __forceinline__ uint32_t pack_bf2(float a, float b) {
    __nv_bfloat162 h = __floats2bfloat162_rn(a, b);
    return *(uint32_t*)&h;
}
__device__ __forceinline__ void ldmx4(uint32_t (&d)[4], uint32_t addr) {
    asm volatile("ldmatrix.sync.aligned.m8n8.x4.shared.b16 {%0,%1,%2,%3}, [%4];"
                 : "=r"(d[0]), "=r"(d[1]), "=r"(d[2]), "=r"(d[3]) : "r"(addr));
}
__device__ __forceinline__ void mma16816(float (&c)[4], const uint32_t (&a)[4],
                                         uint32_t b0, uint32_t b1) {
    asm volatile(
        "mma.sync.aligned.m16n8k16.row.col.f32.bf16.bf16.f32 "
        "{%0,%1,%2,%3}, {%4,%5,%6,%7}, {%8,%9}, {%0,%1,%2,%3};"
        : "+f"(c[0]), "+f"(c[1]), "+f"(c[2]), "+f"(c[3])
        : "r"(a[0]), "r"(a[1]), "r"(a[2]), "r"(a[3]), "r"(b0), "r"(b1));
}
__device__ __forceinline__ uint32_t swz(uint32_t byte) {
    return byte ^ ((byte >> 3) & 0x70);
}
// fp32 tile swizzle: maps thread-fragment writes conflict-free
__device__ __forceinline__ int xm(int r) { return (r & 1) | ((r & 6) << 2); }

__device__ __forceinline__ void cp16(uint32_t dst, const void* src) {
    asm volatile("cp.async.cg.shared.global [%0], [%1], 16;" :: "r"(dst), "l"(src));
}
#define CP_COMMIT() asm volatile("cp.async.commit_group;" ::: "memory")
#define CP_WAIT(n)  asm volatile("cp.async.wait_group %0;" :: "n"(n) : "memory")

template <int ROWS>
__device__ __forceinline__ void stage_cp(uint32_t dst, const __nv_bfloat16* src,
                                         int stride, int tid) {
#pragma unroll
    for (int p = 0; p < ROWS / 32; ++p) {
        int i = tid + p * 256;
        int r = i >> 3, c = i & 7;
        cp16(dst + swz((uint32_t)(r * 128 + c * 16)), src + (size_t)r * stride + c * 8);
    }
}
__device__ __forceinline__ uint32_t tile_addr(uint32_t base, int rowbase, int kbyte, int lane) {
    int mat = lane >> 3, ri = lane & 7;
    int row = rowbase + (mat & 1) * 8 + ri;
    return base + swz((uint32_t)(row * 128 + kbyte + (mat >> 1) * 16));
}

// Warp computes 32x64 over one k=64 chunk, 3 passes (AhiBhi, AloBhi, AhiBlo).
__device__ __forceinline__ void mma_chunk3(float (&acc)[2][8][4],
                                           uint32_t aHi, uint32_t aLo,
                                           uint32_t bHi, uint32_t bLo,
                                           int mrow, int ncol, int lane) {
#pragma unroll
    for (int k16 = 0; k16 < 4; ++k16) {
        int kb = k16 * 32;
        uint32_t ah[2][4], al[2][4];
        ldmx4(ah[0], tile_addr(aHi, mrow, kb, lane));
        ldmx4(ah[1], tile_addr(aHi, mrow + 16, kb, lane));
        ldmx4(al[0], tile_addr(aLo, mrow, kb, lane));
        ldmx4(al[1], tile_addr(aLo, mrow + 16, kb, lane));
#pragma unroll
        for (int gp = 0; gp < 4; gp += 2) {
            uint32_t b0[4], b1[4];
            ldmx4(b0, tile_addr(bHi, ncol + gp * 16, kb, lane));
            ldmx4(b1, tile_addr(bHi, ncol + (gp + 1) * 16, kb, lane));
#pragma unroll
            for (int mi = 0; mi < 2; ++mi) {
                mma16816(acc[mi][gp * 2 + 0], ah[mi], b0[0], b0[2]);
                mma16816(acc[mi][gp * 2 + 1], ah[mi], b0[1], b0[3]);
                mma16816(acc[mi][gp * 2 + 2], ah[mi], b1[0], b1[2]);
                mma16816(acc[mi][gp * 2 + 3], ah[mi], b1[1], b1[3]);
            }
#pragma unroll
            for (int mi = 0; mi < 2; ++mi) {
                mma16816(acc[mi][gp * 2 + 0], al[mi], b0[0], b0[2]);
                mma16816(acc[mi][gp * 2 + 1], al[mi], b0[1], b0[3]);
                mma16816(acc[mi][gp * 2 + 2], al[mi], b1[0], b1[2]);
                mma16816(acc[mi][gp * 2 + 3], al[mi], b1[1], b1[3]);
            }
            uint32_t c0[4], c1[4];
            ldmx4(c0, tile_addr(bLo, ncol + gp * 16, kb, lane));
            ldmx4(c1, tile_addr(bLo, ncol + (gp + 1) * 16, kb, lane));
#pragma unroll
            for (int mi = 0; mi < 2; ++mi) {
                mma16816(acc[mi][gp * 2 + 0], ah[mi], c0[0], c0[2]);
                mma16816(acc[mi][gp * 2 + 1], ah[mi], c0[1], c0[3]);
                mma16816(acc[mi][gp * 2 + 2], ah[mi], c1[0], c1[2]);
                mma16816(acc[mi][gp * 2 + 3], ah[mi], c1[1], c1[3]);
            }
        }
    }
}

// ---------------------------------------------------------------------------
// K1: M = W @ W^T  -> hi/lo bf16
// ---------------------------------------------------------------------------
__global__ void wwt_kernel(const float* __restrict__ W) {
    __shared__ float sR[16][257];
    __shared__ float sC[16][257];
    int tx = threadIdx.x, ty = threadIdx.y;
    int t = ty * 16 + tx;
    int r0 = blockIdx.y * 16, c0 = blockIdx.x * 16;
    {
        int row = t >> 4, base = t & 15;
#pragma unroll
        for (int p = 0; p < 16; ++p) {
            int col = base + p * 16;
            sR[row][col] = W[(r0 + row) * DD + col];
            sC[row][col] = W[(c0 + row) * DD + col];
        }
    }
    __syncthreads();
    float acc = 0.f;
#pragma unroll 8
    for (int k = 0; k < DD; ++k) acc += sR[ty][k] * sC[tx][k];
    float h, l;
    split_hl(acc, h, l);
    d_Mhi[(r0 + ty) * DD + (c0 + tx)] = __float2bfloat16(h);
    d_Mlo[(r0 + ty) * DD + (c0 + tx)] = __float2bfloat16(l);
}

// ---------------------------------------------------------------------------
// K2: X -> Xhi/Xlo (row-major) + Xthi/Xtlo ([b][d][m])
// ---------------------------------------------------------------------------
__global__ __launch_bounds__(256) void convx_kernel(const float* __restrict__ X) {
    __shared__ float tile[32][33];
    int b = blockIdx.z;
    int m0 = blockIdx.y * 32, d0 = blockIdx.x * 32;
    int j = threadIdx.x & 31, i0 = threadIdx.x >> 5;
    const float* Xb = X + (size_t)b * NN * DD;
#pragma unroll
    for (int i = i0; i < 32; i += 8) {
        float v = Xb[(size_t)(m0 + i) * DD + d0 + j];
        tile[i][j] = v;
        float h, l;
        split_hl(v, h, l);
        size_t idx = (size_t)b * NN * DD + (size_t)(m0 + i) * DD + d0 + j;
        d_Xhi[idx] = __float2bfloat16(h);
        d_Xlo[idx] = __float2bfloat16(l);
    }
    __syncthreads();
#pragma unroll
    for (int i = i0; i < 32; i += 8) {
        float v = tile[j][i];
        float h, l;
        split_hl(v, h, l);
        size_t idx = (size_t)b * DD * NN + (size_t)(d0 + i) * NN + m0 + j;
        d_Xthi[idx] = __float2bfloat16(h);
        d_Xtlo[idx] = __float2bfloat16(l);
    }
}

// ---------------------------------------------------------------------------
// K3: G = X @ M.  Single-buffer 64KB, occ 2.  grid (nh=2, tile=256).
// ---------------------------------------------------------------------------
__global__ __launch_bounds__(256, 2) void gproj_kernel() {
    extern __shared__ __align__(128) char sm[];
    uint32_t base = smem_to_u32(sm);
    int tid = threadIdx.x, lane = tid & 31, wid = tid >> 5;
    int nh = blockIdx.x, ti = blockIdx.y;
    int mrow = (wid >> 1) * 32, ncol = (wid & 1) * 64;

    float acc[2][8][4];
#pragma unroll
    for (int mi = 0; mi < 2; ++mi)
#pragma unroll
        for (int nf = 0; nf < 8; ++nf)
#pragma unroll
            for (int q = 0; q < 4; ++q) acc[mi][nf][q] = 0.f;

    const __nv_bfloat16* Ahi = d_Xhi + (size_t)ti * 128 * DD;
    const __nv_bfloat16* Alo = d_Xlo + (size_t)ti * 128 * DD;
    const __nv_bfloat16* Bhi = d_Mhi + nh * 128 * DD;
    const __nv_bfloat16* Blo = d_Mlo + nh * 128 * DD;

    for (int kc = 0; kc < 4; ++kc) {
        stage_cp<128>(base, Ahi + kc * 64, DD, tid);
        stage_cp<128>(base + 16384, Alo + kc * 64, DD, tid);
        stage_cp<128>(base + 32768, Bhi + kc * 64, DD, tid);
        stage_cp<128>(base + 49152, Blo + kc * 64, DD, tid);
        CP_COMMIT();
        CP_WAIT(0);
        __syncthreads();
        mma_chunk3(acc, base, base + 16384, base + 32768, base + 49152, mrow, ncol, lane);
        __syncthreads();
    }
#pragma unroll
    for (int mi = 0; mi < 2; ++mi) {
        int rA = ti * 128 + mrow + mi * 16 + (lane >> 2);
        int rB = rA + 8;
#pragma unroll
        for (int nf = 0; nf < 8; ++nf) {
            int col = nh * 128 + ncol + nf * 8 + (lane & 3) * 2;
            float h0, l0, h1, l1;
            split_hl(acc[mi][nf][0], h0, l0);
            split_hl(acc[mi][nf][1], h1, l1);
            *(uint32_t*)&d_Ghi[(size_t)rA * DD + col] = pack_bf2(h0, h1);
            *(uint32_t*)&d_Glo[(size_t)rA * DD + col] = pack_bf2(l0, l1);
            split_hl(acc[mi][nf][2], h0, l0);
            split_hl(acc[mi][nf][3], h1, l1);
            *(uint32_t*)&d_Ghi[(size_t)rB * DD + col] = pack_bf2(h0, h1);
            *(uint32_t*)&d_Glo[(size_t)rB * DD + col] = pack_bf2(l0, l1);
        }
    }
}

// ---------------------------------------------------------------------------
// K4: scores, UPPER-TRIANGLE tiles only (S_pre symmetric).
// grid (136, 16).  After MMA: leaky -> smem tile -> original block + mirror.
// ---------------------------------------------------------------------------
__global__ __launch_bounds__(256, 2) void scores_kernel(const float* __restrict__ ADJ) {
    extern __shared__ __align__(128) char sm[];
    uint32_t base = smem_to_u32(sm);
    float* sT = (float*)sm;
    int tid = threadIdx.x, lane = tid & 31, wid = tid >> 5;
    int b = blockIdx.y;
    // triangular tile map: t -> (rt, nt) with nt >= rt
    int rt = 0, rem = blockIdx.x;
    while (rem >= 16 - rt) { rem -= 16 - rt; rt++; }
    int nt = rt + rem;
    int mrow = (wid >> 1) * 32, ncol = (wid & 1) * 64;

    float acc[2][8][4];
#pragma unroll
    for (int mi = 0; mi < 2; ++mi)
#pragma unroll
        for (int nf = 0; nf < 8; ++nf)
#pragma unroll
            for (int q = 0; q < 4; ++q) acc[mi][nf][q] = 0.f;

    const __nv_bfloat16* Ahi = d_Ghi + ((size_t)b * NN + rt * 128) * DD;
    const __nv_bfloat16* Alo = d_Glo + ((size_t)b * NN + rt * 128) * DD;
    const __nv_bfloat16* Bhi = d_Xhi + ((size_t)b * NN + nt * 128) * DD;
    const __nv_bfloat16* Blo = d_Xlo + ((size_t)b * NN + nt * 128) * DD;

    for (int kc = 0; kc < 4; ++kc) {
        stage_cp<128>(base, Ahi + kc * 64, DD, tid);
        stage_cp<128>(base + 16384, Alo + kc * 64, DD, tid);
        stage_cp<128>(base + 32768, Bhi + kc * 64, DD, tid);
        stage_cp<128>(base + 49152, Blo + kc * 64, DD, tid);
        CP_COMMIT();
        CP_WAIT(0);
        __syncthreads();
        mma_chunk3(acc, base, base + 16384, base + 32768, base + 49152, mrow, ncol, lane);
        __syncthreads();
    }

    // spill leaky(S_pre) into smem tile (operand buffers are dead now)
#pragma unroll
    for (int mi = 0; mi < 2; ++mi)
#pragma unroll
        for (int nf = 0; nf < 8; ++nf)
#pragma unroll
            for (int q = 0; q < 4; ++q) {
                int r = mrow + mi * 16 + (lane >> 2) + (q >> 1) * 8;
                int c = ncol + nf * 8 + (lane & 3) * 2 + (q & 1);
                float v = acc[mi][nf][q];
                v = fmaxf(v, 0.2f * v);
                sT[r * 128 + (c ^ xm(r))] = v;
            }
    __syncthreads();

    int r = tid >> 1, half = tid & 1;
    // ---- original block: rows rt*128+r, cols nt*128 + half*64.. ----
    {
        int rowg = rt * 128 + r;
        const float* adjp = ADJ + ((size_t)b * NN + rowg) * NN + nt * 128 + half * 64;
        float* sp = d_S + ((size_t)b * NN + rowg) * NN + nt * 128 + half * 64;
        size_t pbase = ((size_t)(b * NN + rowg)) * 64 + nt * 4 + half * 2;
        int xr = xm(r);
#pragma unroll
        for (int cs = 0; cs < 2; ++cs) {
            float v[32];
            float mx = -1e30f;
#pragma unroll
            for (int k = 0; k < 32; k += 4) {
                float4 a = *(const float4*)&adjp[cs * 32 + k];
#pragma unroll
                for (int j = 0; j < 4; ++j) {
                    int c = half * 64 + cs * 32 + k + j;
                    float t = sT[r * 128 + (c ^ xr)] * (&a.x)[j];
                    v[k + j] = t;
                    mx = fmaxf(mx, t);
                }
                *(float4*)&sp[cs * 32 + k] = make_float4(v[k], v[k + 1], v[k + 2], v[k + 3]);
            }
            float s = 0.f;
#pragma unroll
            for (int k = 0; k < 32; ++k) s += __expf(v[k] - mx);
            d_pm[pbase + cs] = mx;
            d_pl[pbase + cs] = s;
        }
    }
    // ---- mirror block (nt > rt): rows nt*128+r, cols rt*128 + half*64.. ----
    if (nt > rt) {
        int rowg = nt * 128 + r;
        const float* adjp = ADJ + ((size_t)b * NN + rowg) * NN + rt * 128 + half * 64;
        float* sp = d_S + ((size_t)b * NN + rowg) * NN + rt * 128 + half * 64;
        size_t pbase = ((size_t)(b * NN + rowg)) * 64 + rt * 4 + half * 2;
#pragma unroll
        for (int cs = 0; cs < 2; ++cs) {
            float v[32];
            float mx = -1e30f;
#pragma unroll
            for (int k = 0; k < 32; k += 4) {
                float4 a = *(const float4*)&adjp[cs * 32 + k];
#pragma unroll
                for (int j = 0; j < 4; ++j) {
                    int c2 = half * 64 + cs * 32 + k + j;   // mirror col = orig row
                    float t = sT[c2 * 128 + (r ^ xm(c2))] * (&a.x)[j];
                    v[k + j] = t;
                    mx = fmaxf(mx, t);
                }
                *(float4*)&sp[cs * 32 + k] = make_float4(v[k], v[k + 1], v[k + 2], v[k + 3]);
            }
            float s = 0.f;
#pragma unroll
            for (int k = 0; k < 32; ++k) s += __expf(v[k] - mx);
            d_pm[pbase + cs] = mx;
            d_pl[pbase + cs] = s;
        }
    }
}

// ---------------------------------------------------------------------------
// K5: merge 64 partials -> d_rm, d_rl
// ---------------------------------------------------------------------------
__global__ void reduce_kernel() {
    int i = blockIdx.x * 256 + threadIdx.x;
    const float* pm = d_pm + ((size_t)i << 6);
    const float* pl = d_pl + ((size_t)i << 6);
    float m = -1e30f;
#pragma unroll
    for (int j = 0; j < 64; ++j) m = fmaxf(m, pm[j]);
    float l = 0.f;
#pragma unroll
    for (int j = 0; j < 64; ++j) l += pl[j] * __expf(pm[j] - m);
    d_rm[i] = m;
    d_rl[i] = l;
}

// ---------------------------------------------------------------------------
// K6: PV.  grid (rt=32, b=16): 64 rows x 256 cols.  P computed inline from S
// while the Xt cp.async is in flight.  Smem: Phi 8K | Plo 8K | Xthi 32K | Xtlo 32K.
// ---------------------------------------------------------------------------
__global__ __launch_bounds__(256, 2) void pv_kernel(const float* __restrict__ bias,
                                                    float* __restrict__ OUT) {
    extern __shared__ __align__(128) char smc[];
    uint32_t base = smem_to_u32(smc);
    int tid = threadIdx.x, lane = tid & 31, wid = tid >> 5;
    int rt = blockIdx.x, b = blockIdx.y;
    int mrow = (wid >> 2) * 32, ncol = (wid & 3) * 64;

    float acc[2][8][4];
#pragma unroll
    for (int mi = 0; mi < 2; ++mi)
#pragma unroll
        for (int nf = 0; nf < 8; ++nf)
#pragma unroll
            for (int q = 0; q < 4; ++q) acc[mi][nf][q] = 0.f;

    const __nv_bfloat16* Bthi = d_Xthi + (size_t)b * DD * NN;
    const __nv_bfloat16* Btlo = d_Xtlo + (size_t)b * DD * NN;

    // per-thread P staging assignment: row pr (0..63), 16 cols at pc
    int pr = tid >> 2, pc = (tid & 3) * 16;
    float mrw = d_rm[b * NN + rt * 64 + pr];
    float linv = 1.f / d_rl[b * NN + rt * 64 + pr];
    const float* sbase = d_S + ((size_t)b * NN + rt * 64 + pr) * NN + pc;
    uint32_t pbyte = swz((uint32_t)(pr * 128 + pc * 2));
    uint32_t pbyte2 = swz((uint32_t)(pr * 128 + pc * 2 + 16));

    for (int kt = 0; kt < 32; ++kt) {
        int k0 = kt * 64;
        // async Xt loads first (overlap with P conversion below)
        stage_cp<256>(base + 16384, Bthi + k0, NN, tid);
        stage_cp<256>(base + 49152, Btlo + k0, NN, tid);
        CP_COMMIT();
        // inline P: p = exp(s - m) / l, hi/lo split into smem
        {
            const float* sp = sbase + k0;
            float p[16];
#pragma unroll
            for (int j = 0; j < 4; ++j) {
                float4 s4 = *(const float4*)&sp[j * 4];
                p[j * 4 + 0] = __expf(s4.x - mrw) * linv;
                p[j * 4 + 1] = __expf(s4.y - mrw) * linv;
                p[j * 4 + 2] = __expf(s4.z - mrw) * linv;
                p[j * 4 + 3] = __expf(s4.w - mrw) * linv;
            }
            uint32_t hi[8], lo[8];
#pragma unroll
            for (int q = 0; q < 8; ++q) {
                float h0, l0, h1, l1;
                split_hl(p[2 * q], h0, l0);
                split_hl(p[2 * q + 1], h1, l1);
                hi[q] = pack_bf2(h0, h1);
                lo[q] = pack_bf2(l0, l1);
            }
            *(uint4*)(smc + pbyte) = make_uint4(hi[0], hi[1], hi[2], hi[3]);
            *(uint4*)(smc + pbyte2) = make_uint4(hi[4], hi[5], hi[6], hi[7]);
            *(uint4*)(smc + 8192 + pbyte) = make_uint4(lo[0], lo[1], lo[2], lo[3]);
            *(uint4*)(smc + 8192 + pbyte2) = make_uint4(lo[4], lo[5], lo[6], lo[7]);
        }
        CP_WAIT(0);
        __syncthreads();
        mma_chunk3(acc, base, base + 8192, base + 16384, base + 49152, mrow, ncol, lane);
        __syncthreads();
    }

#pragma unroll
    for (int mi = 0; mi < 2; ++mi) {
        int rA = rt * 64 + mrow + mi * 16 + (lane >> 2);
        int rB = rA + 8;
#pragma unroll
        for (int nf = 0; nf < 8; ++nf) {
            int col = ncol + nf * 8 + (lane & 3) * 2;
            float2 bv = *(const float2*)&bias[col];
            *(float2*)&OUT[((size_t)b * NN + rA) * DD + col] =
                make_float2(acc[mi][nf][0] + bv.x, acc[mi][nf][1] + bv.y);
            *(float2*)&OUT[((size_t)b * NN + rB) * DD + col] =
                make_float2(acc[mi][nf][2] + bv.x, acc[mi][nf][3] + bv.y);
        }
    }
}

// ---------------------------------------------------------------------------
extern "C" void kernel_launch(void* const* d_in, const int* in_sizes, int n_in,
                              void* d_out, int out_size) {
    const float* x    = (const float*)d_in[0];
    const float* adj  = (const float*)d_in[1];
    const float* W    = (const float*)d_in[2];
    const float* bias = (const float*)d_in[3];
    float* out = (float*)d_out;

    wwt_kernel<<<dim3(16, 16), dim3(16, 16)>>>(W);
    convx_kernel<<<dim3(8, 64, 16), 256>>>(x);

    const int SMB_G = 65536;
    const int SMB_S = 65536;
    const int SMB_P = 81920;
    cudaFuncSetAttribute(gproj_kernel, cudaFuncAttributeMaxDynamicSharedMemorySize, SMB_G);
    cudaFuncSetAttribute(scores_kernel, cudaFuncAttributeMaxDynamicSharedMemorySize, SMB_S);
    cudaFuncSetAttribute(pv_kernel, cudaFuncAttributeMaxDynamicSharedMemorySize, SMB_P);

    gproj_kernel<<<dim3(2, 256), 256, SMB_G>>>();
    scores_kernel<<<dim3(136, 16), 256, SMB_S>>>(adj);
    reduce_kernel<<<BATCH * NN / 256, 256>>>();
    pv_kernel<<<dim3(32, 16), 256, SMB_P>>>(bias, out);
}

// round 9
// speedup vs baseline: 1.2090x; 1.0232x over previous
#include <cuda_runtime.h>
#include <cuda_bf16.h>
#include <cstdint>

#define BATCH 16
#define NN 2048
#define DD 256

// ---------------- scratch (static device globals; no allocs) ----------------
__device__ __nv_bfloat16 d_Mhi[DD * DD];
__device__ __nv_bfloat16 d_Mlo[DD * DD];
__device__ __nv_bfloat16 d_Ghi[BATCH * NN * DD];
__device__ __nv_bfloat16 d_Glo[BATCH * NN * DD];
__device__ __nv_bfloat16 d_Xhi[BATCH * NN * DD];
__device__ __nv_bfloat16 d_Xlo[BATCH * NN * DD];
__device__ __nv_bfloat16 d_Xthi[BATCH * DD * NN];
__device__ __nv_bfloat16 d_Xtlo[BATCH * DD * NN];
__device__ float d_S[(size_t)BATCH * NN * NN];            // 256 MiB scores
__device__ float d_pm[(size_t)BATCH * NN * 32];           // per-(row, 64col-seg) max
__device__ float d_pl[(size_t)BATCH * NN * 32];           // per-(row, 64col-seg) sumexp
__device__ float d_rm[BATCH * NN];
__device__ float d_rl[BATCH * NN];

// ---------------- helpers ----------------
__device__ __forceinline__ uint32_t smem_to_u32(const void* p) {
    uint32_t a;
    asm("{ .reg .u64 t; cvta.to.shared.u64 t, %1; cvt.u32.u64 %0, t; }" : "=r"(a) : "l"(p));
    return a;
}
__device__ __forceinline__ void split_hl(float v, float& h, float& l) {
    __nv_bfloat16 hb = __float2bfloat16(v);
    h = __bfloat162float(hb);
    l = v - h;
}
__device__ __forceinline__ uint32_t pack_bf2(float a, float b) {
    __nv_bfloat162 h = __floats2bfloat162_rn(a, b);
    return *(uint32_t*)&h;
}
__device__ __forceinline__ void ldmx4(uint32_t (&d)[4], uint32_t addr) {
    asm volatile("ldmatrix.sync.aligned.m8n8.x4.shared.b16 {%0,%1,%2,%3}, [%4];"
                 : "=r"(d[0]), "=r"(d[1]), "=r"(d[2]), "=r"(d[3]) : "r"(addr));
}
__device__ __forceinline__ void mma16816(float (&c)[4], const uint32_t (&a)[4],
                                         uint32_t b0, uint32_t b1) {
    asm volatile(
        "mma.sync.aligned.m16n8k16.row.col.f32.bf16.bf16.f32 "
        "{%0,%1,%2,%3}, {%4,%5,%6,%7}, {%8,%9}, {%0,%1,%2,%3};"
        : "+f"(c[0]), "+f"(c[1]), "+f"(c[2]), "+f"(c[3])
        : "r"(a[0]), "r"(a[1]), "r"(a[2]), "r"(a[3]), "r"(b0), "r"(b1));
}
// fp32 mirror-tile swizzle
__device__ __forceinline__ int xm(int r) { return (r & 1) | ((r & 6) << 2); }

__device__ __forceinline__ void cp16(uint32_t dst, const void* src) {
    asm volatile("cp.async.cg.shared.global [%0], [%1], 16;" :: "r"(dst), "l"(src));
}
#define CP_COMMIT() asm volatile("cp.async.commit_group;" ::: "memory")
#define CP_WAIT(n)  asm volatile("cp.async.wait_group %0;" :: "n"(n) : "memory")

// ---- k32 tiles: 64B rows, slot-swizzle: colbyte ^ (((row>>1)&3)<<4) ----
// Stage a [ROWS x 32] bf16 chunk (row stride = stride elems).
template <int ROWS>
__device__ __forceinline__ void stage32(uint32_t dst, const __nv_bfloat16* src,
                                        int stride, int tid) {
#pragma unroll
    for (int p = 0; p < ROWS / 64; ++p) {
        int i = tid + p * 256;
        int r = i >> 2, c = (i & 3) << 4;
        cp16(dst + (uint32_t)(r * 64 + (c ^ (((r >> 1) & 3) << 4))),
             src + (size_t)r * stride + (c >> 1));
    }
}
__device__ __forceinline__ uint32_t tile_addr64(uint32_t base, int rowbase, int kb, int lane) {
    int mat = lane >> 3, ri = lane & 7;
    int row = rowbase + (mat & 1) * 8 + ri;
    int colb = kb + (mat >> 1) * 16;
    return base + (uint32_t)(row * 64 + (colb ^ (((row >> 1) & 3) << 4)));
}

// Warp computes 32x64 over one k=32 chunk, 3 passes.
__device__ __forceinline__ void mma_chunk3_32(float (&acc)[2][8][4],
                                              uint32_t aHi, uint32_t aLo,
                                              uint32_t bHi, uint32_t bLo,
                                              int mrow, int ncol, int lane) {
#pragma unroll
    for (int k16 = 0; k16 < 2; ++k16) {
        int kb = k16 * 32;
        uint32_t ah[2][4], al[2][4];
        ldmx4(ah[0], tile_addr64(aHi, mrow, kb, lane));
        ldmx4(ah[1], tile_addr64(aHi, mrow + 16, kb, lane));
        ldmx4(al[0], tile_addr64(aLo, mrow, kb, lane));
        ldmx4(al[1], tile_addr64(aLo, mrow + 16, kb, lane));
#pragma unroll
        for (int gp = 0; gp < 4; gp += 2) {
            uint32_t b0[4], b1[4];
            ldmx4(b0, tile_addr64(bHi, ncol + gp * 16, kb, lane));
            ldmx4(b1, tile_addr64(bHi, ncol + (gp + 1) * 16, kb, lane));
#pragma unroll
            for (int mi = 0; mi < 2; ++mi) {
                mma16816(acc[mi][gp * 2 + 0], ah[mi], b0[0], b0[2]);
                mma16816(acc[mi][gp * 2 + 1], ah[mi], b0[1], b0[3]);
                mma16816(acc[mi][gp * 2 + 2], ah[mi], b1[0], b1[2]);
                mma16816(acc[mi][gp * 2 + 3], ah[mi], b1[1], b1[3]);
            }
#pragma unroll
            for (int mi = 0; mi < 2; ++mi) {
                mma16816(acc[mi][gp * 2 + 0], al[mi], b0[0], b0[2]);
                mma16816(acc[mi][gp * 2 + 1], al[mi], b0[1], b0[3]);
                mma16816(acc[mi][gp * 2 + 2], al[mi], b1[0], b1[2]);
                mma16816(acc[mi][gp * 2 + 3], al[mi], b1[1], b1[3]);
            }
            uint32_t c0[4], c1[4];
            ldmx4(c0, tile_addr64(bLo, ncol + gp * 16, kb, lane));
            ldmx4(c1, tile_addr64(bLo, ncol + (gp + 1) * 16, kb, lane));
#pragma unroll
            for (int mi = 0; mi < 2; ++mi) {
                mma16816(acc[mi][gp * 2 + 0], ah[mi], c0[0], c0[2]);
                mma16816(acc[mi][gp * 2 + 1], ah[mi], c0[1], c0[3]);
                mma16816(acc[mi][gp * 2 + 2], ah[mi], c1[0], c1[2]);
                mma16816(acc[mi][gp * 2 + 3], ah[mi], c1[1], c1[3]);
            }
        }
    }
}

// ---------------------------------------------------------------------------
// K1: M = W @ W^T  -> hi/lo bf16
// ---------------------------------------------------------------------------
__global__ void wwt_kernel(const float* __restrict__ W) {
    __shared__ float sR[16][257];
    __shared__ float sC[16][257];
    int tx = threadIdx.x, ty = threadIdx.y;
    int t = ty * 16 + tx;
    int r0 = blockIdx.y * 16, c0 = blockIdx.x * 16;
    {
        int row = t >> 4, base = t & 15;
#pragma unroll
        for (int p = 0; p < 16; ++p) {
            int col = base + p * 16;
            sR[row][col] = W[(r0 + row) * DD + col];
            sC[row][col] = W[(c0 + row) * DD + col];
        }
    }
    __syncthreads();
    float acc = 0.f;
#pragma unroll 8
    for (int k = 0; k < DD; ++k) acc += sR[ty][k] * sC[tx][k];
    float h, l;
    split_hl(acc, h, l);
    d_Mhi[(r0 + ty) * DD + (c0 + tx)] = __float2bfloat16(h);
    d_Mlo[(r0 + ty) * DD + (c0 + tx)] = __float2bfloat16(l);
}

// ---------------------------------------------------------------------------
// K2: X -> Xhi/Xlo (row-major) + Xthi/Xtlo ([b][d][m])
// ---------------------------------------------------------------------------
__global__ __launch_bounds__(256) void convx_kernel(const float* __restrict__ X) {
    __shared__ float tile[32][33];
    int b = blockIdx.z;
    int m0 = blockIdx.y * 32, d0 = blockIdx.x * 32;
    int j = threadIdx.x & 31, i0 = threadIdx.x >> 5;
    const float* Xb = X + (size_t)b * NN * DD;
#pragma unroll
    for (int i = i0; i < 32; i += 8) {
        float v = Xb[(size_t)(m0 + i) * DD + d0 + j];
        tile[i][j] = v;
        float h, l;
        split_hl(v, h, l);
        size_t idx = (size_t)b * NN * DD + (size_t)(m0 + i) * DD + d0 + j;
        d_Xhi[idx] = __float2bfloat16(h);
        d_Xlo[idx] = __float2bfloat16(l);
    }
    __syncthreads();
#pragma unroll
    for (int i = i0; i < 32; i += 8) {
        float v = tile[j][i];
        float h, l;
        split_hl(v, h, l);
        size_t idx = (size_t)b * DD * NN + (size_t)(d0 + i) * NN + m0 + j;
        d_Xthi[idx] = __float2bfloat16(h);
        d_Xtlo[idx] = __float2bfloat16(l);
    }
}

// ---------------------------------------------------------------------------
// K3: G = X @ M.  k32 double-buffered, occ 2.  grid (nh=2, tile=256).
// Set layout: Ahi 0 | Alo 8K | Bhi 16K | Blo 24K  (32KB/set)
// ---------------------------------------------------------------------------
__global__ __launch_bounds__(256, 2) void gproj_kernel() {
    extern __shared__ __align__(128) char sm[];
    uint32_t base = smem_to_u32(sm);
    int tid = threadIdx.x, lane = tid & 31, wid = tid >> 5;
    int nh = blockIdx.x, ti = blockIdx.y;
    int mrow = (wid >> 1) * 32, ncol = (wid & 1) * 64;

    float acc[2][8][4];
#pragma unroll
    for (int mi = 0; mi < 2; ++mi)
#pragma unroll
        for (int nf = 0; nf < 8; ++nf)
#pragma unroll
            for (int q = 0; q < 4; ++q) acc[mi][nf][q] = 0.f;

    const __nv_bfloat16* Ahi = d_Xhi + (size_t)ti * 128 * DD;
    const __nv_bfloat16* Alo = d_Xlo + (size_t)ti * 128 * DD;
    const __nv_bfloat16* Bhi = d_Mhi + nh * 128 * DD;
    const __nv_bfloat16* Blo = d_Mlo + nh * 128 * DD;

    stage32<128>(base, Ahi, DD, tid);
    stage32<128>(base + 8192, Alo, DD, tid);
    stage32<128>(base + 16384, Bhi, DD, tid);
    stage32<128>(base + 24576, Blo, DD, tid);
    CP_COMMIT();

    for (int kc = 0; kc < 8; ++kc) {
        if (kc < 7) {
            uint32_t nb = base + ((kc + 1) & 1) * 32768;
            int k0 = (kc + 1) * 32;
            stage32<128>(nb, Ahi + k0, DD, tid);
            stage32<128>(nb + 8192, Alo + k0, DD, tid);
            stage32<128>(nb + 16384, Bhi + k0, DD, tid);
            stage32<128>(nb + 24576, Blo + k0, DD, tid);
            CP_COMMIT();
            CP_WAIT(1);
        } else {
            CP_WAIT(0);
        }
        __syncthreads();
        uint32_t cb = base + (kc & 1) * 32768;
        mma_chunk3_32(acc, cb, cb + 8192, cb + 16384, cb + 24576, mrow, ncol, lane);
        __syncthreads();
    }
#pragma unroll
    for (int mi = 0; mi < 2; ++mi) {
        int rA = ti * 128 + mrow + mi * 16 + (lane >> 2);
        int rB = rA + 8;
#pragma unroll
        for (int nf = 0; nf < 8; ++nf) {
            int col = nh * 128 + ncol + nf * 8 + (lane & 3) * 2;
            float h0, l0, h1, l1;
            split_hl(acc[mi][nf][0], h0, l0);
            split_hl(acc[mi][nf][1], h1, l1);
            *(uint32_t*)&d_Ghi[(size_t)rA * DD + col] = pack_bf2(h0, h1);
            *(uint32_t*)&d_Glo[(size_t)rA * DD + col] = pack_bf2(l0, l1);
            split_hl(acc[mi][nf][2], h0, l0);
            split_hl(acc[mi][nf][3], h1, l1);
            *(uint32_t*)&d_Ghi[(size_t)rB * DD + col] = pack_bf2(h0, h1);
            *(uint32_t*)&d_Glo[(size_t)rB * DD + col] = pack_bf2(l0, l1);
        }
    }
}

// ---------------------------------------------------------------------------
// K4: scores, upper-triangle tiles, k32 double-buffered.
// Epilogue: original block from fragments; mirror via smem sT (reuses buffers).
// ---------------------------------------------------------------------------
__global__ __launch_bounds__(256, 2) void scores_kernel(const float* __restrict__ ADJ) {
    extern __shared__ __align__(128) char sm[];
    uint32_t base = smem_to_u32(sm);
    float* sT = (float*)sm;
    int tid = threadIdx.x, lane = tid & 31, wid = tid >> 5;
    int b = blockIdx.y;
    int rt = 0, rem = blockIdx.x;
    while (rem >= 16 - rt) { rem -= 16 - rt; rt++; }
    int nt = rt + rem;
    int mrow = (wid >> 1) * 32, ncol = (wid & 1) * 64;

    float acc[2][8][4];
#pragma unroll
    for (int mi = 0; mi < 2; ++mi)
#pragma unroll
        for (int nf = 0; nf < 8; ++nf)
#pragma unroll
            for (int q = 0; q < 4; ++q) acc[mi][nf][q] = 0.f;

    const __nv_bfloat16* Ahi = d_Ghi + ((size_t)b * NN + rt * 128) * DD;
    const __nv_bfloat16* Alo = d_Glo + ((size_t)b * NN + rt * 128) * DD;
    const __nv_bfloat16* Bhi = d_Xhi + ((size_t)b * NN + nt * 128) * DD;
    const __nv_bfloat16* Blo = d_Xlo + ((size_t)b * NN + nt * 128) * DD;

    stage32<128>(base, Ahi, DD, tid);
    stage32<128>(base + 8192, Alo, DD, tid);
    stage32<128>(base + 16384, Bhi, DD, tid);
    stage32<128>(base + 24576, Blo, DD, tid);
    CP_COMMIT();

    for (int kc = 0; kc < 8; ++kc) {
        if (kc < 7) {
            uint32_t nb = base + ((kc + 1) & 1) * 32768;
            int k0 = (kc + 1) * 32;
            stage32<128>(nb, Ahi + k0, DD, tid);
            stage32<128>(nb + 8192, Alo + k0, DD, tid);
            stage32<128>(nb + 16384, Bhi + k0, DD, tid);
            stage32<128>(nb + 24576, Blo + k0, DD, tid);
            CP_COMMIT();
            CP_WAIT(1);
        } else {
            CP_WAIT(0);
        }
        __syncthreads();
        uint32_t cb = base + (kc & 1) * 32768;
        mma_chunk3_32(acc, cb, cb + 8192, cb + 16384, cb + 24576, mrow, ncol, lane);
        __syncthreads();
    }

    // apply leaky; spill to sT for mirror (keep post-leaky in acc)
#pragma unroll
    for (int mi = 0; mi < 2; ++mi)
#pragma unroll
        for (int nf = 0; nf < 8; ++nf)
#pragma unroll
            for (int q = 0; q < 4; ++q) {
                int r = mrow + mi * 16 + (lane >> 2) + (q >> 1) * 8;
                int c = ncol + nf * 8 + (lane & 3) * 2 + (q & 1);
                float v = acc[mi][nf][q];
                v = fmaxf(v, 0.2f * v);
                acc[mi][nf][q] = v;
                sT[r * 128 + (c ^ xm(r))] = v;
            }
    __syncthreads();

    // ---- original block: fragments -> *adj -> S + 64col partials ----
    {
        int cb0 = nt * 128 + ncol + (lane & 3) * 2;
        float mx[2][2] = {{-1e30f, -1e30f}, {-1e30f, -1e30f}};
#pragma unroll
        for (int mi = 0; mi < 2; ++mi) {
            int rA = rt * 128 + mrow + mi * 16 + (lane >> 2);
            int rB = rA + 8;
            const float* adjA = ADJ + ((size_t)b * NN + rA) * NN;
            const float* adjB = ADJ + ((size_t)b * NN + rB) * NN;
            float* swA = d_S + ((size_t)b * NN + rA) * NN;
            float* swB = d_S + ((size_t)b * NN + rB) * NN;
#pragma unroll
            for (int nf = 0; nf < 8; ++nf) {
                int c = cb0 + nf * 8;
                float2 aA = *(const float2*)&adjA[c];
                float2 aB = *(const float2*)&adjB[c];
                float v0 = acc[mi][nf][0] * aA.x;
                float v1 = acc[mi][nf][1] * aA.y;
                float v2 = acc[mi][nf][2] * aB.x;
                float v3 = acc[mi][nf][3] * aB.y;
                acc[mi][nf][0] = v0; acc[mi][nf][1] = v1;
                acc[mi][nf][2] = v2; acc[mi][nf][3] = v3;
                *(float2*)&swA[c] = make_float2(v0, v1);
                *(float2*)&swB[c] = make_float2(v2, v3);
                mx[mi][0] = fmaxf(mx[mi][0], fmaxf(v0, v1));
                mx[mi][1] = fmaxf(mx[mi][1], fmaxf(v2, v3));
            }
        }
#pragma unroll
        for (int mi = 0; mi < 2; ++mi)
#pragma unroll
            for (int h = 0; h < 2; ++h) {
                mx[mi][h] = fmaxf(mx[mi][h], __shfl_xor_sync(0xffffffffu, mx[mi][h], 1));
                mx[mi][h] = fmaxf(mx[mi][h], __shfl_xor_sync(0xffffffffu, mx[mi][h], 2));
            }
        float sum[2][2] = {{0.f, 0.f}, {0.f, 0.f}};
#pragma unroll
        for (int mi = 0; mi < 2; ++mi)
#pragma unroll
            for (int nf = 0; nf < 8; ++nf) {
                sum[mi][0] += __expf(acc[mi][nf][0] - mx[mi][0]) + __expf(acc[mi][nf][1] - mx[mi][0]);
                sum[mi][1] += __expf(acc[mi][nf][2] - mx[mi][1]) + __expf(acc[mi][nf][3] - mx[mi][1]);
            }
#pragma unroll
        for (int mi = 0; mi < 2; ++mi)
#pragma unroll
            for (int h = 0; h < 2; ++h) {
                sum[mi][h] += __shfl_xor_sync(0xffffffffu, sum[mi][h], 1);
                sum[mi][h] += __shfl_xor_sync(0xffffffffu, sum[mi][h], 2);
            }
        if ((lane & 3) == 0) {
            int pi = nt * 2 + (wid & 1);
#pragma unroll
            for (int mi = 0; mi < 2; ++mi)
#pragma unroll
                for (int h = 0; h < 2; ++h) {
                    int row = rt * 128 + mrow + mi * 16 + (lane >> 2) + h * 8;
                    size_t idx = (((size_t)b * NN + row) << 5) + pi;
                    d_pm[idx] = mx[mi][h];
                    d_pl[idx] = sum[mi][h];
                }
        }
    }

    // ---- mirror block (nt > rt): rows nt*128+r, cols rt*128.. ----
    if (nt > rt) {
        int r = tid >> 1, half = tid & 1;
        int rowg = nt * 128 + r;
        const float* adjp = ADJ + ((size_t)b * NN + rowg) * NN + rt * 128 + half * 64;
        float* sp = d_S + ((size_t)b * NN + rowg) * NN + rt * 128 + half * 64;
        float mcs[2], scs[2];
#pragma unroll
        for (int cs = 0; cs < 2; ++cs) {
            float v[32];
            float mx = -1e30f;
#pragma unroll
            for (int k = 0; k < 32; k += 4) {
                float4 a = *(const float4*)&adjp[cs * 32 + k];
#pragma unroll
                for (int j = 0; j < 4; ++j) {
                    int c2 = half * 64 + cs * 32 + k + j;   // mirror col = orig row
                    float t = sT[c2 * 128 + (r ^ xm(c2))] * (&a.x)[j];
                    v[k + j] = t;
                    mx = fmaxf(mx, t);
                }
                *(float4*)&sp[cs * 32 + k] = make_float4(v[k], v[k + 1], v[k + 2], v[k + 3]);
            }
            float s = 0.f;
#pragma unroll
            for (int k = 0; k < 32; ++k) s += __expf(v[k] - mx);
            mcs[cs] = mx;
            scs[cs] = s;
        }
        float m = fmaxf(mcs[0], mcs[1]);
        float s = scs[0] * __expf(mcs[0] - m) + scs[1] * __expf(mcs[1] - m);
        size_t idx = (((size_t)(b * NN + rowg)) << 5) + rt * 2 + half;
        d_pm[idx] = m;
        d_pl[idx] = s;
    }
}

// ---------------------------------------------------------------------------
// K5: merge 32 partials -> d_rm, d_rl
// ---------------------------------------------------------------------------
__global__ void reduce_kernel() {
    int i = blockIdx.x * 256 + threadIdx.x;
    const float* pm = d_pm + ((size_t)i << 5);
    const float* pl = d_pl + ((size_t)i << 5);
    float m = -1e30f;
#pragma unroll
    for (int j = 0; j < 32; ++j) m = fmaxf(m, pm[j]);
    float l = 0.f;
#pragma unroll
    for (int j = 0; j < 32; ++j) l += pl[j] * __expf(pm[j] - m);
    d_rm[i] = m;
    d_rl[i] = l;
}

// ---------------------------------------------------------------------------
// K6: PV.  k32 double-buffered, occ 2.  grid (rt=32, b=16): 64 x 256.
// Set layout: Phi 0 | Plo 4K | Xthi 8K | Xtlo 24K  (40KB/set)
// ---------------------------------------------------------------------------
__global__ __launch_bounds__(256, 2) void pv_kernel(const float* __restrict__ bias,
                                                    float* __restrict__ OUT) {
    extern __shared__ __align__(128) char smc[];
    uint32_t base = smem_to_u32(smc);
    int tid = threadIdx.x, lane = tid & 31, wid = tid >> 5;
    int rt = blockIdx.x, b = blockIdx.y;
    int mrow = (wid >> 2) * 32, ncol = (wid & 3) * 64;

    float acc[2][8][4];
#pragma unroll
    for (int mi = 0; mi < 2; ++mi)
#pragma unroll
        for (int nf = 0; nf < 8; ++nf)
#pragma unroll
            for (int q = 0; q < 4; ++q) acc[mi][nf][q] = 0.f;

    const __nv_bfloat16* Bthi = d_Xthi + (size_t)b * DD * NN;
    const __nv_bfloat16* Btlo = d_Xtlo + (size_t)b * DD * NN;

    // P conversion assignment: row pr (0..63), 8 cols at pc
    int pr = tid >> 2, pc = (tid & 3) * 8;
    float mrw = d_rm[b * NN + rt * 64 + pr];
    float linv = 1.f / d_rl[b * NN + rt * 64 + pr];
    const float* sbase = d_S + ((size_t)b * NN + rt * 64 + pr) * NN + pc;
    uint32_t pbyte = (uint32_t)(pr * 64 + (((tid & 3) * 16) ^ (((pr >> 1) & 3) << 4)));

    // prologue: chunk 0
    stage32<256>(base + 8192, Bthi, NN, tid);
    stage32<256>(base + 24576, Btlo, NN, tid);
    CP_COMMIT();
    {
        float p[8];
        float4 s0 = *(const float4*)&sbase[0];
        float4 s1 = *(const float4*)&sbase[4];
        p[0] = __expf(s0.x - mrw) * linv; p[1] = __expf(s0.y - mrw) * linv;
        p[2] = __expf(s0.z - mrw) * linv; p[3] = __expf(s0.w - mrw) * linv;
        p[4] = __expf(s1.x - mrw) * linv; p[5] = __expf(s1.y - mrw) * linv;
        p[6] = __expf(s1.z - mrw) * linv; p[7] = __expf(s1.w - mrw) * linv;
        uint32_t hi[4], lo[4];
#pragma unroll
        for (int q = 0; q < 4; ++q) {
            float h0, l0, h1, l1;
            split_hl(p[2 * q], h0, l0);
            split_hl(p[2 * q + 1], h1, l1);
            hi[q] = pack_bf2(h0, h1);
            lo[q] = pack_bf2(l0, l1);
        }
        *(uint4*)(smc + pbyte) = make_uint4(hi[0], hi[1], hi[2], hi[3]);
        *(uint4*)(smc + 4096 + pbyte) = make_uint4(lo[0], lo[1], lo[2], lo[3]);
    }

    for (int kt = 0; kt < 64; ++kt) {
        if (kt < 63) {
            int nset = (kt + 1) & 1;
            uint32_t nb = base + nset * 40960;
            int k0 = (kt + 1) * 32;
            stage32<256>(nb + 8192, Bthi + k0, NN, tid);
            stage32<256>(nb + 24576, Btlo + k0, NN, tid);
            CP_COMMIT();
            // inline P for next chunk into next set
            float p[8];
            float4 s0 = *(const float4*)&sbase[k0];
            float4 s1 = *(const float4*)&sbase[k0 + 4];
            p[0] = __expf(s0.x - mrw) * linv; p[1] = __expf(s0.y - mrw) * linv;
            p[2] = __expf(s0.z - mrw) * linv; p[3] = __expf(s0.w - mrw) * linv;
            p[4] = __expf(s1.x - mrw) * linv; p[5] = __expf(s1.y - mrw) * linv;
            p[6] = __expf(s1.z - mrw) * linv; p[7] = __expf(s1.w - mrw) * linv;
            uint32_t hi[4], lo[4];
#pragma unroll
            for (int q = 0; q < 4; ++q) {
                float h0, l0, h1, l1;
                split_hl(p[2 * q], h0, l0);
                split_hl(p[2 * q + 1], h1, l1);
                hi[q] = pack_bf2(h0, h1);
                lo[q] = pack_bf2(l0, l1);
            }
            *(uint4*)(smc + nset * 40960 + pbyte) = make_uint4(hi[0], hi[1], hi[2], hi[3]);
            *(uint4*)(smc + nset * 40960 + 4096 + pbyte) = make_uint4(lo[0], lo[1], lo[2], lo[3]);
            CP_WAIT(1);
        } else {
            CP_WAIT(0);
        }
        __syncthreads();
        uint32_t cb = base + (kt & 1) * 40960;
        mma_chunk3_32(acc, cb, cb + 4096, cb + 8192, cb + 24576, mrow, ncol, lane);
        __syncthreads();
    }

#pragma unroll
    for (int mi = 0; mi < 2; ++mi) {
        int rA = rt * 64 + mrow + mi * 16 + (lane >> 2);
        int rB = rA + 8;
#pragma unroll
        for (int nf = 0; nf < 8; ++nf) {
            int col = ncol + nf * 8 + (lane & 3) * 2;
            float2 bv = *(const float2*)&bias[col];
            *(float2*)&OUT[((size_t)b * NN + rA) * DD + col] =
                make_float2(acc[mi][nf][0] + bv.x, acc[mi][nf][1] + bv.y);
            *(float2*)&OUT[((size_t)b * NN + rB) * DD + col] =
                make_float2(acc[mi][nf][2] + bv.x, acc[mi][nf][3] + bv.y);
        }
    }
}

// ---------------------------------------------------------------------------
extern "C" void kernel_launch(void* const* d_in, const int* in_sizes, int n_in,
                              void* d_out, int out_size) {
    const float* x    = (const float*)d_in[0];
    const float* adj  = (const float*)d_in[1];
    const float* W    = (const float*)d_in[2];
    const float* bias = (const float*)d_in[3];
    float* out = (float*)d_out;

    wwt_kernel<<<dim3(16, 16), dim3(16, 16)>>>(W);
    convx_kernel<<<dim3(8, 64, 16), 256>>>(x);

    const int SMB_G = 65536;   // 2 x 32KB
    const int SMB_S = 65536;   // 2 x 32KB (sT reuses the same region)
    const int SMB_P = 81920;   // 2 x 40KB
    cudaFuncSetAttribute(gproj_kernel, cudaFuncAttributeMaxDynamicSharedMemorySize, SMB_G);
    cudaFuncSetAttribute(scores_kernel, cudaFuncAttributeMaxDynamicSharedMemorySize, SMB_S);
    cudaFuncSetAttribute(pv_kernel, cudaFuncAttributeMaxDynamicSharedMemorySize, SMB_P);

    gproj_kernel<<<dim3(2, 256), 256, SMB_G>>>();
    scores_kernel<<<dim3(136, 16), 256, SMB_S>>>(adj);
    reduce_kernel<<<BATCH * NN / 256, 256>>>();
    pv_kernel<<<dim3(32, 16), 256, SMB_P>>>(bias, out);
}